// round 1
// baseline (speedup 1.0000x reference)
#include <cuda_runtime.h>
#include <math.h>

// ---------------- problem constants ----------------
#define BB   2
#define LL   1024
#define DM_  1024
#define DI_  2048
#define NS   16
#define MR   (BB * LL)        // 2048 rows (b*L+t)
#define DTR_ 64

// ---------------- scratch (no allocations allowed) ----------------
// offsets in floats
#define OFF_XN     0                      // (MR, DM)            2,097,152
#define OFF_XZ     (OFF_XN + 2097152)     // (MR, 2*DI)          8,388,608
#define OFF_XCONV  (OFF_XZ + 8388608)     // (MR, DI)            4,194,304
#define OFF_DTIN   (OFF_XCONV + 4194304)  // (MR, DTR)             131,072
#define OFF_DT     (OFF_DTIN + 131072)    // (MR, DI)            4,194,304
#define OFF_BCW    (OFF_DT + 4194304)     // (32, DI)               65,536
#define OFF_BCM    (OFF_BCW + 65536)      // (MR, 32)               65,536
#define OFF_Y      (OFF_BCM + 65536)      // (MR, DI)            4,194,304
#define SCRATCH_FLOATS (OFF_Y + 4194304)

__device__ float g_scratch[SCRATCH_FLOATS];

// ---------------- LayerNorm ----------------
__global__ void ln_kernel(const float* __restrict__ x, const float* __restrict__ g,
                          const float* __restrict__ b, float* __restrict__ o) {
    int row = blockIdx.x;                       // 0..MR-1
    int tid = threadIdx.x;                      // 256 threads, 4 floats each
    const float4* xr = (const float4*)(x + (size_t)row * DM_);
    float4 v = xr[tid];
    float s  = v.x + v.y + v.z + v.w;
    float ss = v.x * v.x + v.y * v.y + v.z * v.z + v.w * v.w;
    #pragma unroll
    for (int off = 16; off > 0; off >>= 1) {
        s  += __shfl_xor_sync(0xffffffffu, s,  off);
        ss += __shfl_xor_sync(0xffffffffu, ss, off);
    }
    __shared__ float sh_s[8], sh_ss[8];
    int w = tid >> 5, l = tid & 31;
    if (l == 0) { sh_s[w] = s; sh_ss[w] = ss; }
    __syncthreads();
    if (w == 0) {
        s  = (l < 8) ? sh_s[l]  : 0.f;
        ss = (l < 8) ? sh_ss[l] : 0.f;
        #pragma unroll
        for (int off = 4; off > 0; off >>= 1) {
            s  += __shfl_xor_sync(0xffffffffu, s,  off);
            ss += __shfl_xor_sync(0xffffffffu, ss, off);
        }
        if (l == 0) { sh_s[0] = s; sh_ss[0] = ss; }
    }
    __syncthreads();
    float mu  = sh_s[0] * (1.0f / DM_);
    float var = sh_ss[0] * (1.0f / DM_) - mu * mu;
    float inv = rsqrtf(var + 1e-5f);
    float4 gg = ((const float4*)g)[tid];
    float4 bb = ((const float4*)b)[tid];
    float4 r;
    r.x = (v.x - mu) * inv * gg.x + bb.x;
    r.y = (v.y - mu) * inv * gg.y + bb.y;
    r.z = (v.z - mu) * inv * gg.z + bb.z;
    r.w = (v.w - mu) * inv * gg.w + bb.w;
    ((float4*)(o + (size_t)row * DM_))[tid] = r;
}

// ---------------- tiled fp32 GEMM, C[M,N] = A[M,K] * B[N,K]^T ----------------
// Both operands row-major with K contiguous ("NT" layout). Requires
// M%BM==0, N%BN==0, K%BK==0, BK%4==0.
enum { EPI_NONE = 0, EPI_BIAS = 1, EPI_SOFTPLUS = 2, EPI_RES = 3 };

template<int BM, int BN, int BK, int TM, int TN, int EPI>
__global__ void __launch_bounds__((BM / TM) * (BN / TN))
gemm_nt(const float* __restrict__ A, const float* __restrict__ Bw,
        float* __restrict__ C, int M, int N, int K,
        const float* __restrict__ bias, const float* __restrict__ res) {
    constexpr int THREADS = (BM / TM) * (BN / TN);
    constexpr int AQ = BM * BK / 4;
    constexpr int BQ = BN * BK / 4;
    static_assert(AQ % THREADS == 0 || AQ >= THREADS, "A tile load");
    constexpr int AITER = (AQ + THREADS - 1) / THREADS;
    constexpr int BITER = (BQ + THREADS - 1) / THREADS;

    __shared__ float As[BK][BM + 4];
    __shared__ float Bs[BK][BN + 4];

    const int bm  = blockIdx.y * BM;
    const int bn  = blockIdx.x * BN;
    const int tid = threadIdx.x;
    const int tx  = tid % (BN / TN);
    const int ty  = tid / (BN / TN);

    float acc[TM][TN];
    #pragma unroll
    for (int i = 0; i < TM; i++)
        #pragma unroll
        for (int j = 0; j < TN; j++) acc[i][j] = 0.f;

    for (int k0 = 0; k0 < K; k0 += BK) {
        #pragma unroll
        for (int it = 0; it < AITER; it++) {
            int idx = tid + it * THREADS;
            if (AQ % THREADS == 0 || idx < AQ) {
                int r = idx / (BK / 4);
                int q = idx % (BK / 4);
                float4 v = *(const float4*)(A + (size_t)(bm + r) * K + k0 + q * 4);
                As[q * 4 + 0][r] = v.x;
                As[q * 4 + 1][r] = v.y;
                As[q * 4 + 2][r] = v.z;
                As[q * 4 + 3][r] = v.w;
            }
        }
        #pragma unroll
        for (int it = 0; it < BITER; it++) {
            int idx = tid + it * THREADS;
            if (BQ % THREADS == 0 || idx < BQ) {
                int r = idx / (BK / 4);
                int q = idx % (BK / 4);
                float4 v = *(const float4*)(Bw + (size_t)(bn + r) * K + k0 + q * 4);
                Bs[q * 4 + 0][r] = v.x;
                Bs[q * 4 + 1][r] = v.y;
                Bs[q * 4 + 2][r] = v.z;
                Bs[q * 4 + 3][r] = v.w;
            }
        }
        __syncthreads();
        #pragma unroll
        for (int k = 0; k < BK; k++) {
            float a[TM], b[TN];
            #pragma unroll
            for (int i = 0; i < TM; i++) a[i] = As[k][ty * TM + i];
            #pragma unroll
            for (int j = 0; j < TN; j++) b[j] = Bs[k][tx * TN + j];
            #pragma unroll
            for (int i = 0; i < TM; i++)
                #pragma unroll
                for (int j = 0; j < TN; j++)
                    acc[i][j] = fmaf(a[i], b[j], acc[i][j]);
        }
        __syncthreads();
    }

    #pragma unroll
    for (int i = 0; i < TM; i++) {
        int m = bm + ty * TM + i;
        #pragma unroll
        for (int j = 0; j < TN; j++) {
            int n = bn + tx * TN + j;
            float v = acc[i][j];
            if (EPI == EPI_BIAS) {
                v += bias[n];
            } else if (EPI == EPI_SOFTPLUS) {
                v += bias[n];
                v = (v > 20.f) ? v : log1pf(expf(v));
            } else if (EPI == EPI_RES) {
                v += res[(size_t)m * N + n];
            }
            C[(size_t)m * N + n] = v;
        }
    }
}

// ---------------- causal depthwise conv (k=4) + SiLU ----------------
__global__ void conv_silu_kernel(const float* __restrict__ xz,   // (MR, 2*DI), x_proj = first DI
                                 const float* __restrict__ w,    // (DI, 1, 4)
                                 const float* __restrict__ cb,   // (DI)
                                 float* __restrict__ xc) {       // (MR, DI)
    int idx = blockIdx.x * blockDim.x + threadIdx.x;
    if (idx >= BB * LL * DI_) return;
    int d = idx % DI_;
    int t = (idx / DI_) % LL;
    int b = idx / (DI_ * LL);
    const float* base = xz + (size_t)b * LL * (2 * DI_) + d;
    float acc = cb[d];
    #pragma unroll
    for (int k = 0; k < 4; k++) {
        int ts = t - 3 + k;
        if (ts >= 0) acc = fmaf(w[d * 4 + k], base[(size_t)ts * (2 * DI_)], acc);
    }
    float sg = 1.f / (1.f + __expf(-acc));
    xc[idx] = acc * sg;
}

// ---------------- concat B_w | C_w into (32, DI) ----------------
__global__ void concat_bc_kernel(const float* __restrict__ Bw, const float* __restrict__ Cw,
                                 float* __restrict__ bcw) {
    int i = blockIdx.x * blockDim.x + threadIdx.x;
    if (i < NS * DI_)            bcw[i] = Bw[i];
    else if (i < 2 * NS * DI_)   bcw[i] = Cw[i - NS * DI_];
}

// ---------------- selective scan + SiLU(z) gating ----------------
// One channel (b,d) per half-warp; lane = state index n (0..15).
__global__ void scan_kernel(const float* __restrict__ xconv,  // (MR, DI)  = u
                            const float* __restrict__ dt,     // (MR, DI)
                            const float* __restrict__ bcm,    // (MR, 32)  [B | C]
                            const float* __restrict__ A_log,  // (DI, 16)
                            const float* __restrict__ Dp,     // (DI)
                            const float* __restrict__ xz,     // (MR, 2*DI), z = second DI
                            float* __restrict__ y) {          // (MR, DI) gated output
    int half = threadIdx.x >> 4;                 // 16 channels per 256-thread block
    int lane = threadIdx.x & 15;
    int ch = blockIdx.x * (blockDim.x >> 4) + half;   // 0 .. BB*DI-1
    int b = ch / DI_;
    int d = ch % DI_;

    float a  = -expf(A_log[d * NS + lane]);
    float Dd = Dp[d];
    float h  = 0.f;

    const float* dtp = dt    + (size_t)b * LL * DI_ + d;
    const float* up  = xconv + (size_t)b * LL * DI_ + d;
    const float* bcp = bcm   + (size_t)b * LL * 32;
    const float* zp  = xz    + (size_t)b * LL * (2 * DI_) + DI_ + d;
    float*       yp  = y     + (size_t)b * LL * DI_ + d;

    for (int t = 0; t < LL; t++) {
        float dtv = dtp[(size_t)t * DI_];
        float uv  = up[(size_t)t * DI_];
        float Bn  = bcp[t * 32 + lane];
        float Cn  = bcp[t * 32 + 16 + lane];
        float dA  = __expf(dtv * a);
        h = fmaf(h, dA, dtv * uv * Bn);
        float p = h * Cn;
        p += __shfl_xor_sync(0xffffffffu, p, 8);
        p += __shfl_xor_sync(0xffffffffu, p, 4);
        p += __shfl_xor_sync(0xffffffffu, p, 2);
        p += __shfl_xor_sync(0xffffffffu, p, 1);
        if (lane == 0) {
            float zv = zp[(size_t)t * (2 * DI_)];
            float sz = zv / (1.f + __expf(-zv));
            yp[(size_t)t * DI_] = (p + uv * Dd) * sz;
        }
    }
}

// ---------------- launch ----------------
extern "C" void kernel_launch(void* const* d_in, const int* in_sizes, int n_in,
                              void* d_out, int out_size) {
    const float* x         = (const float*)d_in[0];
    const float* ln_g      = (const float*)d_in[1];
    const float* ln_b      = (const float*)d_in[2];
    const float* in_proj_w = (const float*)d_in[3];
    const float* conv_w    = (const float*)d_in[4];
    const float* conv_b    = (const float*)d_in[5];
    const float* dtin_w    = (const float*)d_in[6];
    const float* dtin_b    = (const float*)d_in[7];
    const float* dt_w      = (const float*)d_in[8];
    const float* dt_b      = (const float*)d_in[9];
    const float* B_w       = (const float*)d_in[10];
    const float* C_w       = (const float*)d_in[11];
    const float* A_log     = (const float*)d_in[12];
    const float* Dp        = (const float*)d_in[13];
    const float* out_w     = (const float*)d_in[14];
    float* out = (float*)d_out;

    float* s = nullptr;
    cudaGetSymbolAddress((void**)&s, g_scratch);
    float* xn    = s + OFF_XN;
    float* xz    = s + OFF_XZ;
    float* xconv = s + OFF_XCONV;
    float* dtin  = s + OFF_DTIN;
    float* dt    = s + OFF_DT;
    float* bcw   = s + OFF_BCW;
    float* bcm   = s + OFF_BCM;
    float* y     = s + OFF_Y;

    // 1) LayerNorm
    ln_kernel<<<MR, 256>>>(x, ln_g, ln_b, xn);

    // 2) xz = xn @ in_proj_w^T : (2048, 4096)
    {
        dim3 grid(4096 / 128, MR / 128);
        gemm_nt<128, 128, 16, 8, 8, EPI_NONE><<<grid, 256>>>(
            xn, in_proj_w, xz, MR, 2 * DI_, DM_, nullptr, nullptr);
    }

    // 3) causal conv + SiLU
    conv_silu_kernel<<<(BB * LL * DI_ + 255) / 256, 256>>>(xz, conv_w, conv_b, xconv);

    // 4) concat [B_w ; C_w]
    concat_bc_kernel<<<(2 * NS * DI_ + 255) / 256, 256>>>(B_w, C_w, bcw);

    // 5) dt_in = xconv @ dtin_w^T + dtin_b : (2048, 64)
    {
        dim3 grid(DTR_ / 64, MR / 64);
        gemm_nt<64, 64, 16, 4, 4, EPI_BIAS><<<grid, 256>>>(
            xconv, dtin_w, dtin, MR, DTR_, DI_, dtin_b, nullptr);
    }

    // 6) dt = softplus(dt_in @ dt_w^T + dt_b) : (2048, 2048)
    {
        dim3 grid(DI_ / 128, MR / 128);
        gemm_nt<128, 128, 16, 8, 8, EPI_SOFTPLUS><<<grid, 256>>>(
            dtin, dt_w, dt, MR, DI_, DTR_, dt_b, nullptr);
    }

    // 7) [B | C] = xconv @ bcw^T : (2048, 32)
    {
        dim3 grid(32 / 32, MR / 64);
        gemm_nt<64, 32, 16, 4, 4, EPI_NONE><<<grid, 128>>>(
            xconv, bcw, bcm, MR, 32, DI_, nullptr, nullptr);
    }

    // 8) selective scan + SiLU(z) gating -> y
    scan_kernel<<<(BB * DI_) / 16, 256>>>(xconv, dt, bcm, A_log, Dp, xz, y);

    // 9) out = y @ out_w^T + residual(x) : (2048, 1024)
    {
        dim3 grid(DM_ / 128, MR / 128);
        gemm_nt<128, 128, 16, 8, 8, EPI_RES><<<grid, 256>>>(
            y, out_w, out, MR, DM_, DI_, nullptr, x);
    }
}

// round 2
// speedup vs baseline: 1.5782x; 1.5782x over previous
#include <cuda_runtime.h>
#include <math.h>
#include <stdint.h>

// ---------------- problem constants ----------------
#define BB   2
#define LL   1024
#define DM_  1024
#define DI_  2048
#define NS   16
#define MR   (BB * LL)        // 2048 rows (b*L+t)
#define DTR_ 64
#define KSPLIT 8

// ---------------- scratch (no allocations allowed) ----------------
#define OFF_XN      0                       // (MR, DM)
#define OFF_XZ      (OFF_XN + 2097152)      // (MR, 2*DI)
#define OFF_XCONV   (OFF_XZ + 8388608)      // (MR, DI)
#define OFF_DTIN    (OFF_XCONV + 4194304)   // (MR, DTR)
#define OFF_DT      (OFF_DTIN + 131072)     // (MR, DI)
#define OFF_BCW     (OFF_DT + 4194304)      // (32, DI)
#define OFF_BCM     (OFF_BCW + 65536)       // (MR, 32)
#define OFF_Y       (OFF_BCM + 65536)       // (MR, DI)
#define OFF_DTIN_P  (OFF_Y + 4194304)       // (KSPLIT, MR, DTR)
#define OFF_BCM_P   (OFF_DTIN_P + 1048576)  // (KSPLIT, MR, 32)
#define SCRATCH_FLOATS (OFF_BCM_P + 524288)

__device__ float g_scratch[SCRATCH_FLOATS];

// ---------------- helpers ----------------
__device__ __forceinline__ unsigned f2tf32(float f) {
    unsigned u;
    asm("cvt.rna.tf32.f32 %0, %1;" : "=r"(u) : "f"(f));
    return u;
}

// ---------------- LayerNorm ----------------
__global__ void ln_kernel(const float* __restrict__ x, const float* __restrict__ g,
                          const float* __restrict__ b, float* __restrict__ o) {
    int row = blockIdx.x;
    int tid = threadIdx.x;                      // 256 threads, 4 floats each
    const float4* xr = (const float4*)(x + (size_t)row * DM_);
    float4 v = xr[tid];
    float s  = v.x + v.y + v.z + v.w;
    float ss = v.x * v.x + v.y * v.y + v.z * v.z + v.w * v.w;
    #pragma unroll
    for (int off = 16; off > 0; off >>= 1) {
        s  += __shfl_xor_sync(0xffffffffu, s,  off);
        ss += __shfl_xor_sync(0xffffffffu, ss, off);
    }
    __shared__ float sh_s[8], sh_ss[8];
    int w = tid >> 5, l = tid & 31;
    if (l == 0) { sh_s[w] = s; sh_ss[w] = ss; }
    __syncthreads();
    if (w == 0) {
        s  = (l < 8) ? sh_s[l]  : 0.f;
        ss = (l < 8) ? sh_ss[l] : 0.f;
        #pragma unroll
        for (int off = 4; off > 0; off >>= 1) {
            s  += __shfl_xor_sync(0xffffffffu, s,  off);
            ss += __shfl_xor_sync(0xffffffffu, ss, off);
        }
        if (l == 0) { sh_s[0] = s; sh_ss[0] = ss; }
    }
    __syncthreads();
    float mu  = sh_s[0] * (1.0f / DM_);
    float var = sh_ss[0] * (1.0f / DM_) - mu * mu;
    float inv = rsqrtf(var + 1e-5f);
    float4 gg = ((const float4*)g)[tid];
    float4 bb = ((const float4*)b)[tid];
    float4 r;
    r.x = (v.x - mu) * inv * gg.x + bb.x;
    r.y = (v.y - mu) * inv * gg.y + bb.y;
    r.z = (v.z - mu) * inv * gg.z + bb.z;
    r.w = (v.w - mu) * inv * gg.w + bb.w;
    ((float4*)(o + (size_t)row * DM_))[tid] = r;
}

// ---------------- TF32 tensor-core GEMM, C[M,N] = A[M,K] * B[N,K]^T ----------------
// Both operands row-major, K contiguous. 256 threads = 8 warps (2 x 4).
// BK = 32, mma.m16n8k8.tf32. Smem swizzle: chunk' = chunk ^ (row & 7)
// (chunk = 4-float group) -> conflict-free float4 staging stores and
// conflict-free scalar fragment loads.
enum { EPI_NONE = 0, EPI_BIAS = 1, EPI_SOFTPLUS = 2, EPI_RES = 3 };

template<int BM, int BN, int EPI, bool SPLITK>
__global__ void __launch_bounds__(256)
mma_nt(const float* __restrict__ A, const float* __restrict__ Bw,
       float* __restrict__ C, int M, int N, int K,
       const float* __restrict__ bias, const float* __restrict__ res,
       int ksplit_len) {
    constexpr int THREADS = 256;
    constexpr int BK = 32;
    constexpr int WARPS_M = 2, WARPS_N = 4;
    constexpr int WM = BM / WARPS_M;          // 64
    constexpr int WN = BN / WARPS_N;          // 32/16/8
    constexpr int MI = WM / 16;               // 4
    constexpr int NI = WN / 8;                // 4/2/1
    constexpr int ALD = BM * 8 / THREADS;     // float4 loads per thread for A
    constexpr int BLD = BN * 8 / THREADS;     // for B
    static_assert(ALD >= 1 && BLD >= 1, "tile/thread mismatch");

    __shared__ unsigned smA[BM * BK];
    __shared__ unsigned smB[BN * BK];

    const int tid  = threadIdx.x;
    const int warp = tid >> 5, lane = tid & 31;
    const int g  = lane >> 2, tg = lane & 3;
    const int wm = (warp % WARPS_M) * WM;
    const int wn = (warp / WARPS_M) * WN;
    const int bm = blockIdx.y * BM;
    const int bn = blockIdx.x * BN;

    int k_begin = 0, k_len = K;
    if (SPLITK) { k_begin = blockIdx.z * ksplit_len; k_len = ksplit_len; }

    // per-thread swizzled column offsets: chunk (2*kk+h) ^ g, scalar tg
    int col[4][2];
    #pragma unroll
    for (int kk = 0; kk < 4; kk++) {
        col[kk][0] = ((((2 * kk    ) ^ g) << 2) | tg);
        col[kk][1] = ((((2 * kk + 1) ^ g) << 2) | tg);
    }
    int rowA[MI], rowB[NI];
    #pragma unroll
    for (int mi = 0; mi < MI; mi++) rowA[mi] = (wm + mi * 16 + g) * BK;
    #pragma unroll
    for (int ni = 0; ni < NI; ni++) rowB[ni] = (wn + ni * 8 + g) * BK;

    float c[MI][NI][4];
    #pragma unroll
    for (int mi = 0; mi < MI; mi++)
        #pragma unroll
        for (int ni = 0; ni < NI; ni++)
            #pragma unroll
            for (int q = 0; q < 4; q++) c[mi][ni][q] = 0.f;

    const float* Ag = A  + (size_t)bm * K + k_begin;
    const float* Bg = Bw + (size_t)bn * K + k_begin;

    float4 ra[ALD], rb[BLD];

    // prologue: load first tiles
    #pragma unroll
    for (int i = 0; i < ALD; i++) {
        int idx = tid + i * THREADS;
        ra[i] = *(const float4*)(Ag + (size_t)(idx >> 3) * K + ((idx & 7) << 2));
    }
    #pragma unroll
    for (int i = 0; i < BLD; i++) {
        int idx = tid + i * THREADS;
        rb[i] = *(const float4*)(Bg + (size_t)(idx >> 3) * K + ((idx & 7) << 2));
    }

    for (int k0 = 0; k0 < k_len; k0 += BK) {
        // stage registers -> smem (with tf32 rounding)
        #pragma unroll
        for (int i = 0; i < ALD; i++) {
            int idx = tid + i * THREADS;
            int r = idx >> 3, ch = idx & 7;
            uint4 v = { f2tf32(ra[i].x), f2tf32(ra[i].y), f2tf32(ra[i].z), f2tf32(ra[i].w) };
            *(uint4*)&smA[r * BK + ((ch ^ (r & 7)) << 2)] = v;
        }
        #pragma unroll
        for (int i = 0; i < BLD; i++) {
            int idx = tid + i * THREADS;
            int r = idx >> 3, ch = idx & 7;
            uint4 v = { f2tf32(rb[i].x), f2tf32(rb[i].y), f2tf32(rb[i].z), f2tf32(rb[i].w) };
            *(uint4*)&smB[r * BK + ((ch ^ (r & 7)) << 2)] = v;
        }
        __syncthreads();

        // prefetch next tiles while computing
        if (k0 + BK < k_len) {
            #pragma unroll
            for (int i = 0; i < ALD; i++) {
                int idx = tid + i * THREADS;
                ra[i] = *(const float4*)(Ag + (size_t)(idx >> 3) * K + k0 + BK + ((idx & 7) << 2));
            }
            #pragma unroll
            for (int i = 0; i < BLD; i++) {
                int idx = tid + i * THREADS;
                rb[i] = *(const float4*)(Bg + (size_t)(idx >> 3) * K + k0 + BK + ((idx & 7) << 2));
            }
        }

        #pragma unroll
        for (int kk = 0; kk < 4; kk++) {
            unsigned af[MI][4], bf[NI][2];
            #pragma unroll
            for (int mi = 0; mi < MI; mi++) {
                af[mi][0] = smA[rowA[mi]       + col[kk][0]];
                af[mi][1] = smA[rowA[mi] + 256 + col[kk][0]];   // +8 rows
                af[mi][2] = smA[rowA[mi]       + col[kk][1]];
                af[mi][3] = smA[rowA[mi] + 256 + col[kk][1]];
            }
            #pragma unroll
            for (int ni = 0; ni < NI; ni++) {
                bf[ni][0] = smB[rowB[ni] + col[kk][0]];
                bf[ni][1] = smB[rowB[ni] + col[kk][1]];
            }
            #pragma unroll
            for (int mi = 0; mi < MI; mi++)
                #pragma unroll
                for (int ni = 0; ni < NI; ni++) {
                    asm volatile(
                        "mma.sync.aligned.m16n8k8.row.col.f32.tf32.tf32.f32 "
                        "{%0,%1,%2,%3}, {%4,%5,%6,%7}, {%8,%9}, {%0,%1,%2,%3};"
                        : "+f"(c[mi][ni][0]), "+f"(c[mi][ni][1]),
                          "+f"(c[mi][ni][2]), "+f"(c[mi][ni][3])
                        : "r"(af[mi][0]), "r"(af[mi][1]), "r"(af[mi][2]), "r"(af[mi][3]),
                          "r"(bf[ni][0]), "r"(bf[ni][1]));
                }
        }
        __syncthreads();
    }

    // epilogue
    float* Cb = C;
    if (SPLITK) Cb += (size_t)blockIdx.z * (size_t)M * N;
    #pragma unroll
    for (int mi = 0; mi < MI; mi++) {
        #pragma unroll
        for (int ni = 0; ni < NI; ni++) {
            int coln = bn + wn + ni * 8 + tg * 2;
            #pragma unroll
            for (int h = 0; h < 2; h++) {
                int row = bm + wm + mi * 16 + g + h * 8;
                float v0 = c[mi][ni][2 * h + 0];
                float v1 = c[mi][ni][2 * h + 1];
                if (EPI == EPI_BIAS) {
                    v0 += bias[coln]; v1 += bias[coln + 1];
                } else if (EPI == EPI_SOFTPLUS) {
                    v0 += bias[coln]; v1 += bias[coln + 1];
                    v0 = (v0 > 20.f) ? v0 : log1pf(expf(v0));
                    v1 = (v1 > 20.f) ? v1 : log1pf(expf(v1));
                } else if (EPI == EPI_RES) {
                    float2 rr = *(const float2*)&res[(size_t)row * N + coln];
                    v0 += rr.x; v1 += rr.y;
                }
                float2 out = { v0, v1 };
                *(float2*)&Cb[(size_t)row * N + coln] = out;
            }
        }
    }
}

// ---------------- split-K reduce (+ optional bias) ----------------
__global__ void reduce_kernel(const float* __restrict__ part, float* __restrict__ out,
                              const float* __restrict__ bias, int MN, int Ncols) {
    int i = blockIdx.x * blockDim.x + threadIdx.x;
    if (i >= MN) return;
    float s = bias ? bias[i % Ncols] : 0.f;
    #pragma unroll
    for (int p = 0; p < KSPLIT; p++) s += part[(size_t)p * MN + i];
    out[i] = s;
}

// ---------------- causal depthwise conv (k=4) + SiLU ----------------
__global__ void conv_silu_kernel(const float* __restrict__ xz,
                                 const float* __restrict__ w,
                                 const float* __restrict__ cb,
                                 float* __restrict__ xc) {
    int idx = blockIdx.x * blockDim.x + threadIdx.x;
    if (idx >= BB * LL * DI_) return;
    int d = idx % DI_;
    int t = (idx / DI_) % LL;
    int b = idx / (DI_ * LL);
    const float* base = xz + (size_t)b * LL * (2 * DI_) + d;
    float acc = cb[d];
    #pragma unroll
    for (int k = 0; k < 4; k++) {
        int ts = t - 3 + k;
        if (ts >= 0) acc = fmaf(w[d * 4 + k], base[(size_t)ts * (2 * DI_)], acc);
    }
    float sg = 1.f / (1.f + __expf(-acc));
    xc[idx] = acc * sg;
}

// ---------------- concat B_w | C_w into (32, DI) ----------------
__global__ void concat_bc_kernel(const float* __restrict__ Bw, const float* __restrict__ Cw,
                                 float* __restrict__ bcw) {
    int i = blockIdx.x * blockDim.x + threadIdx.x;
    if (i < NS * DI_)            bcw[i] = Bw[i];
    else if (i < 2 * NS * DI_)   bcw[i] = Cw[i - NS * DI_];
}

// ---------------- selective scan + SiLU(z) gating ----------------
__global__ void scan_kernel(const float* __restrict__ xconv,
                            const float* __restrict__ dt,
                            const float* __restrict__ bcm,
                            const float* __restrict__ A_log,
                            const float* __restrict__ Dp,
                            const float* __restrict__ xz,
                            float* __restrict__ y) {
    int half = threadIdx.x >> 4;
    int lane = threadIdx.x & 15;
    int ch = blockIdx.x * (blockDim.x >> 4) + half;
    int b = ch / DI_;
    int d = ch % DI_;

    float a  = -expf(A_log[d * NS + lane]);
    float Dd = Dp[d];
    float h  = 0.f;

    const float* dtp = dt    + (size_t)b * LL * DI_ + d;
    const float* up  = xconv + (size_t)b * LL * DI_ + d;
    const float* bcp = bcm   + (size_t)b * LL * 32;
    const float* zp  = xz    + (size_t)b * LL * (2 * DI_) + DI_ + d;
    float*       yp  = y     + (size_t)b * LL * DI_ + d;

    for (int t = 0; t < LL; t++) {
        float dtv = dtp[(size_t)t * DI_];
        float uv  = up[(size_t)t * DI_];
        float Bn  = bcp[t * 32 + lane];
        float Cn  = bcp[t * 32 + 16 + lane];
        float dA  = __expf(dtv * a);
        h = fmaf(h, dA, dtv * uv * Bn);
        float p = h * Cn;
        p += __shfl_xor_sync(0xffffffffu, p, 8);
        p += __shfl_xor_sync(0xffffffffu, p, 4);
        p += __shfl_xor_sync(0xffffffffu, p, 2);
        p += __shfl_xor_sync(0xffffffffu, p, 1);
        if (lane == 0) {
            float zv = zp[(size_t)t * (2 * DI_)];
            float sz = zv / (1.f + __expf(-zv));
            yp[(size_t)t * DI_] = (p + uv * Dd) * sz;
        }
    }
}

// ---------------- launch ----------------
extern "C" void kernel_launch(void* const* d_in, const int* in_sizes, int n_in,
                              void* d_out, int out_size) {
    const float* x         = (const float*)d_in[0];
    const float* ln_g      = (const float*)d_in[1];
    const float* ln_b      = (const float*)d_in[2];
    const float* in_proj_w = (const float*)d_in[3];
    const float* conv_w    = (const float*)d_in[4];
    const float* conv_b    = (const float*)d_in[5];
    const float* dtin_w    = (const float*)d_in[6];
    const float* dtin_b    = (const float*)d_in[7];
    const float* dt_w      = (const float*)d_in[8];
    const float* dt_b      = (const float*)d_in[9];
    const float* B_w       = (const float*)d_in[10];
    const float* C_w       = (const float*)d_in[11];
    const float* A_log     = (const float*)d_in[12];
    const float* Dp        = (const float*)d_in[13];
    const float* out_w     = (const float*)d_in[14];
    float* out = (float*)d_out;

    float* s = nullptr;
    cudaGetSymbolAddress((void**)&s, g_scratch);
    float* xn     = s + OFF_XN;
    float* xz     = s + OFF_XZ;
    float* xconv  = s + OFF_XCONV;
    float* dtin   = s + OFF_DTIN;
    float* dt     = s + OFF_DT;
    float* bcw    = s + OFF_BCW;
    float* bcm    = s + OFF_BCM;
    float* y      = s + OFF_Y;
    float* dtin_p = s + OFF_DTIN_P;
    float* bcm_p  = s + OFF_BCM_P;

    // 1) LayerNorm
    ln_kernel<<<MR, 256>>>(x, ln_g, ln_b, xn);

    // 2) xz = xn @ in_proj_w^T : (2048, 4096), K=1024
    {
        dim3 grid(4096 / 128, MR / 128);
        mma_nt<128, 128, EPI_NONE, false><<<grid, 256>>>(
            xn, in_proj_w, xz, MR, 4096, DM_, nullptr, nullptr, 0);
    }

    // 3) causal conv + SiLU
    conv_silu_kernel<<<(BB * LL * DI_ + 255) / 256, 256>>>(xz, conv_w, conv_b, xconv);

    // 4) concat [B_w ; C_w]
    concat_bc_kernel<<<(2 * NS * DI_ + 255) / 256, 256>>>(B_w, C_w, bcw);

    // 5) dt_in partials: xconv @ dtin_w^T : (2048, 64), K=2048, split-K=8
    {
        dim3 grid(1, MR / 128, KSPLIT);
        mma_nt<128, 64, EPI_NONE, true><<<grid, 256>>>(
            xconv, dtin_w, dtin_p, MR, DTR_, DI_, nullptr, nullptr, DI_ / KSPLIT);
        reduce_kernel<<<(MR * DTR_ + 255) / 256, 256>>>(dtin_p, dtin, dtin_b, MR * DTR_, DTR_);
    }

    // 6) dt = softplus(dt_in @ dt_w^T + dt_b) : (2048, 2048), K=64
    {
        dim3 grid(DI_ / 128, MR / 128);
        mma_nt<128, 128, EPI_SOFTPLUS, false><<<grid, 256>>>(
            dtin, dt_w, dt, MR, DI_, DTR_, dt_b, nullptr, 0);
    }

    // 7) [B | C] partials: xconv @ bcw^T : (2048, 32), K=2048, split-K=8
    {
        dim3 grid(1, MR / 128, KSPLIT);
        mma_nt<128, 32, EPI_NONE, true><<<grid, 256>>>(
            xconv, bcw, bcm_p, MR, 32, DI_, nullptr, nullptr, DI_ / KSPLIT);
        reduce_kernel<<<(MR * 32 + 255) / 256, 256>>>(bcm_p, bcm, nullptr, MR * 32, 32);
    }

    // 8) selective scan + SiLU(z) gating -> y
    scan_kernel<<<(BB * DI_) / 16, 256>>>(xconv, dt, bcm, A_log, Dp, xz, y);

    // 9) out = y @ out_w^T + residual(x) : (2048, 1024), K=2048
    {
        dim3 grid(DM_ / 64, MR / 128);
        mma_nt<128, 64, EPI_RES, false><<<grid, 256>>>(
            y, out_w, out, MR, DM_, DI_, nullptr, x, 0);
    }
}

// round 4
// speedup vs baseline: 3.2342x; 2.0492x over previous
#include <cuda_runtime.h>
#include <cuda_fp16.h>
#include <math.h>
#include <stdint.h>

// ---------------- problem constants ----------------
#define BB   2
#define LL   1024
#define DM_  1024
#define DI_  2048
#define NS   16
#define MR   (BB * LL)        // 2048 rows (b*L+t)
#define DTR_ 64
#define KSPLIT 8

// ---------------- scratch ----------------
#define OFF_XN      0                       // (MR, DM)
#define OFF_XZ      (OFF_XN + 2097152)      // (MR, 2*DI)
#define OFF_XCONV   (OFF_XZ + 8388608)      // (MR, DI)
#define OFF_DTIN    (OFF_XCONV + 4194304)   // (MR, DTR)
#define OFF_DT      (OFF_DTIN + 131072)     // (MR, DI)
#define OFF_BCM     (OFF_DT + 4194304)      // (MR, 32)
#define OFF_Y       (OFF_BCM + 65536)       // (MR, DI)
#define OFF_DTIN_P  (OFF_Y + 4194304)       // (KSPLIT, MR, DTR)
#define OFF_BCM_P   (OFF_DTIN_P + 1048576)  // (KSPLIT, MR, 32)
#define SCRATCH_FLOATS (OFF_BCM_P + 524288)

__device__ float g_scratch[SCRATCH_FLOATS];

// pack two floats to fp16x2 (round-to-nearest), lo = a, hi = b
__device__ __forceinline__ uint32_t pack_h2(float a, float b) {
    uint32_t p;
    asm("cvt.rn.f16x2.f32 %0, %1, %2;" : "=r"(p) : "f"(b), "f"(a));
    return p;
}

// ---------------- LayerNorm ----------------
__global__ void ln_kernel(const float* __restrict__ x, const float* __restrict__ g,
                          const float* __restrict__ b, float* __restrict__ o) {
    int row = blockIdx.x;
    int tid = threadIdx.x;
    const float4* xr = (const float4*)(x + (size_t)row * DM_);
    float4 v = xr[tid];
    float s  = v.x + v.y + v.z + v.w;
    float ss = v.x * v.x + v.y * v.y + v.z * v.z + v.w * v.w;
    #pragma unroll
    for (int off = 16; off > 0; off >>= 1) {
        s  += __shfl_xor_sync(0xffffffffu, s,  off);
        ss += __shfl_xor_sync(0xffffffffu, ss, off);
    }
    __shared__ float sh_s[8], sh_ss[8];
    int w = tid >> 5, l = tid & 31;
    if (l == 0) { sh_s[w] = s; sh_ss[w] = ss; }
    __syncthreads();
    if (w == 0) {
        s  = (l < 8) ? sh_s[l]  : 0.f;
        ss = (l < 8) ? sh_ss[l] : 0.f;
        #pragma unroll
        for (int off = 4; off > 0; off >>= 1) {
            s  += __shfl_xor_sync(0xffffffffu, s,  off);
            ss += __shfl_xor_sync(0xffffffffu, ss, off);
        }
        if (l == 0) { sh_s[0] = s; sh_ss[0] = ss; }
    }
    __syncthreads();
    float mu  = sh_s[0] * (1.0f / DM_);
    float var = sh_ss[0] * (1.0f / DM_) - mu * mu;
    float inv = rsqrtf(var + 1e-5f);
    float4 gg = ((const float4*)g)[tid];
    float4 bb = ((const float4*)b)[tid];
    float4 r;
    r.x = (v.x - mu) * inv * gg.x + bb.x;
    r.y = (v.y - mu) * inv * gg.y + bb.y;
    r.z = (v.z - mu) * inv * gg.z + bb.z;
    r.w = (v.w - mu) * inv * gg.w + bb.w;
    ((float4*)(o + (size_t)row * DM_))[tid] = r;
}

// ---------------- fp16 tensor-core GEMM: C[M,N] = A[M,K] * B[N,K]^T ----------------
// BM=128, BK=32 (16 fp16x2 words / row = 64B rows), mma.m16n8k16.
// smem word layout: idx = r*16 + ((chunk ^ ((r>>1)&3))<<2) + off  (chunk = idx/4)
// -> conflict-free 16B staging stores AND conflict-free fragment LDS.
enum { EPI_NONE = 0, EPI_BIAS = 1, EPI_SOFTPLUS = 2, EPI_RES = 3 };

template<int BN, int EPI, bool SPLITK, bool BCAT>
__global__ void __launch_bounds__(256)
hmma_nt(const float* __restrict__ A, const float* __restrict__ Bw,
        const float* __restrict__ Bw2, float* __restrict__ C,
        int M, int N, int K,
        const float* __restrict__ bias, const float* __restrict__ res,
        int ksplit_len) {
    constexpr int BK = 32;
    constexpr int WM = 64;               // 2 warps in M
    constexpr int WN = BN / 4;           // 4 warps in N
    constexpr int MI = WM / 16;          // 4
    constexpr int NI = WN / 8;           // 4 / 2 / 1
    constexpr int ACH = 128 * 4;         // 16B chunks in A tile (512)
    constexpr int BCH = BN * 4;          // 16B chunks in B tile
    constexpr int AITER = ACH / 256;     // 2
    constexpr int BITER = (BCH + 255) / 256;

    __shared__ uint32_t smA[128 * 16];
    __shared__ uint32_t smB[BN * 16];

    const int tid  = threadIdx.x;
    const int warp = tid >> 5, lane = tid & 31;
    const int g  = lane >> 2, tg = lane & 3;
    const int wm = (warp & 1) * WM;
    const int wn = (warp >> 1) * WN;
    const int bm = blockIdx.y * 128;
    const int bn = blockIdx.x * BN;
    const int swz = (g >> 1) & 3;

    int k_begin = 0, k_len = K;
    if (SPLITK) { k_begin = blockIdx.z * ksplit_len; k_len = ksplit_len; }

    int rowA[MI], rowB[NI];
    #pragma unroll
    for (int mi = 0; mi < MI; mi++) rowA[mi] = (wm + mi * 16 + g) * 16;
    #pragma unroll
    for (int ni = 0; ni < NI; ni++) rowB[ni] = (wn + ni * 8 + g) * 16;

    float c[MI][NI][4];
    #pragma unroll
    for (int mi = 0; mi < MI; mi++)
        #pragma unroll
        for (int ni = 0; ni < NI; ni++)
            #pragma unroll
            for (int q = 0; q < 4; q++) c[mi][ni][q] = 0.f;

    const float* Ag = A + (size_t)bm * K + k_begin;

    // prefetch first tiles into registers (8 floats per chunk)
    float4 fa[AITER][2], fb[BITER][2];
    #pragma unroll
    for (int i = 0; i < AITER; i++) {
        int idx = tid + i * 256;
        int r = idx >> 2, ch = idx & 3;
        const float* p = Ag + (size_t)r * K + ch * 8;
        fa[i][0] = *(const float4*)p;
        fa[i][1] = *(const float4*)(p + 4);
    }
    #pragma unroll
    for (int i = 0; i < BITER; i++) {
        int idx = tid + i * 256;
        if (BCH % 256 == 0 || idx < BCH) {
            int r = idx >> 2, ch = idx & 3;
            const float* src;
            if (BCAT) src = (r < NS) ? (Bw + (size_t)r * K) : (Bw2 + (size_t)(r - NS) * K);
            else      src = Bw + (size_t)(bn + r) * K;
            src += k_begin + ch * 8;
            fb[i][0] = *(const float4*)src;
            fb[i][1] = *(const float4*)(src + 4);
        }
    }

    for (int k0 = 0; k0 < k_len; k0 += BK) {
        // stage registers -> smem as fp16x2
        #pragma unroll
        for (int i = 0; i < AITER; i++) {
            int idx = tid + i * 256;
            int r = idx >> 2, ch = idx & 3;
            uint4 u = { pack_h2(fa[i][0].x, fa[i][0].y), pack_h2(fa[i][0].z, fa[i][0].w),
                        pack_h2(fa[i][1].x, fa[i][1].y), pack_h2(fa[i][1].z, fa[i][1].w) };
            *(uint4*)&smA[r * 16 + ((ch ^ ((r >> 1) & 3)) << 2)] = u;
        }
        #pragma unroll
        for (int i = 0; i < BITER; i++) {
            int idx = tid + i * 256;
            if (BCH % 256 == 0 || idx < BCH) {
                int r = idx >> 2, ch = idx & 3;
                uint4 u = { pack_h2(fb[i][0].x, fb[i][0].y), pack_h2(fb[i][0].z, fb[i][0].w),
                            pack_h2(fb[i][1].x, fb[i][1].y), pack_h2(fb[i][1].z, fb[i][1].w) };
                *(uint4*)&smB[r * 16 + ((ch ^ ((r >> 1) & 3)) << 2)] = u;
            }
        }
        __syncthreads();

        // prefetch next tiles
        if (k0 + BK < k_len) {
            #pragma unroll
            for (int i = 0; i < AITER; i++) {
                int idx = tid + i * 256;
                int r = idx >> 2, ch = idx & 3;
                const float* p = Ag + (size_t)r * K + k0 + BK + ch * 8;
                fa[i][0] = *(const float4*)p;
                fa[i][1] = *(const float4*)(p + 4);
            }
            #pragma unroll
            for (int i = 0; i < BITER; i++) {
                int idx = tid + i * 256;
                if (BCH % 256 == 0 || idx < BCH) {
                    int r = idx >> 2, ch = idx & 3;
                    const float* src;
                    if (BCAT) src = (r < NS) ? (Bw + (size_t)r * K) : (Bw2 + (size_t)(r - NS) * K);
                    else      src = Bw + (size_t)(bn + r) * K;
                    src += k_begin + k0 + BK + ch * 8;
                    fb[i][0] = *(const float4*)src;
                    fb[i][1] = *(const float4*)(src + 4);
                }
            }
        }

        // compute: 2 k-steps of 16
        #pragma unroll
        for (int kk = 0; kk < 2; kk++) {
            const int c0 = (((2 * kk) ^ swz) << 2) + tg;
            const int c1 = (((2 * kk + 1) ^ swz) << 2) + tg;
            uint32_t af[MI][4], bf[NI][2];
            #pragma unroll
            for (int mi = 0; mi < MI; mi++) {
                af[mi][0] = smA[rowA[mi]       + c0];
                af[mi][1] = smA[rowA[mi] + 128 + c0];   // +8 rows
                af[mi][2] = smA[rowA[mi]       + c1];
                af[mi][3] = smA[rowA[mi] + 128 + c1];
            }
            #pragma unroll
            for (int ni = 0; ni < NI; ni++) {
                bf[ni][0] = smB[rowB[ni] + c0];
                bf[ni][1] = smB[rowB[ni] + c1];
            }
            #pragma unroll
            for (int mi = 0; mi < MI; mi++)
                #pragma unroll
                for (int ni = 0; ni < NI; ni++) {
                    asm volatile(
                        "mma.sync.aligned.m16n8k16.row.col.f32.f16.f16.f32 "
                        "{%0,%1,%2,%3}, {%4,%5,%6,%7}, {%8,%9}, {%0,%1,%2,%3};"
                        : "+f"(c[mi][ni][0]), "+f"(c[mi][ni][1]),
                          "+f"(c[mi][ni][2]), "+f"(c[mi][ni][3])
                        : "r"(af[mi][0]), "r"(af[mi][1]), "r"(af[mi][2]), "r"(af[mi][3]),
                          "r"(bf[ni][0]), "r"(bf[ni][1]));
                }
        }
        __syncthreads();
    }

    // epilogue
    float* Cb = C;
    if (SPLITK) Cb += (size_t)blockIdx.z * (size_t)M * N;
    #pragma unroll
    for (int mi = 0; mi < MI; mi++) {
        #pragma unroll
        for (int ni = 0; ni < NI; ni++) {
            int coln = bn + wn + ni * 8 + tg * 2;
            #pragma unroll
            for (int h = 0; h < 2; h++) {
                int row = bm + wm + mi * 16 + g + h * 8;
                float v0 = c[mi][ni][2 * h + 0];
                float v1 = c[mi][ni][2 * h + 1];
                if (EPI == EPI_BIAS) {
                    v0 += bias[coln]; v1 += bias[coln + 1];
                } else if (EPI == EPI_SOFTPLUS) {
                    v0 += bias[coln]; v1 += bias[coln + 1];
                    v0 = (v0 > 20.f) ? v0 : log1pf(expf(v0));
                    v1 = (v1 > 20.f) ? v1 : log1pf(expf(v1));
                } else if (EPI == EPI_RES) {
                    float2 rr = *(const float2*)&res[(size_t)row * N + coln];
                    v0 += rr.x; v1 += rr.y;
                }
                float2 out = { v0, v1 };
                *(float2*)&Cb[(size_t)row * N + coln] = out;
            }
        }
    }
}

// ---------------- split-K reduce (+ optional bias) ----------------
__global__ void reduce_kernel(const float* __restrict__ part, float* __restrict__ out,
                              const float* __restrict__ bias, int MN, int Ncols) {
    int i = blockIdx.x * blockDim.x + threadIdx.x;
    if (i >= MN) return;
    float s = bias ? bias[i % Ncols] : 0.f;
    #pragma unroll
    for (int p = 0; p < KSPLIT; p++) s += part[(size_t)p * MN + i];
    out[i] = s;
}

// ---------------- causal depthwise conv (k=4) + SiLU ----------------
__global__ void conv_silu_kernel(const float* __restrict__ xz,
                                 const float* __restrict__ w,
                                 const float* __restrict__ cb,
                                 float* __restrict__ xc) {
    int idx = blockIdx.x * blockDim.x + threadIdx.x;
    if (idx >= BB * LL * DI_) return;
    int d = idx % DI_;
    int t = (idx / DI_) % LL;
    int b = idx / (DI_ * LL);
    const float* base = xz + (size_t)b * LL * (2 * DI_) + d;
    float acc = cb[d];
    #pragma unroll
    for (int k = 0; k < 4; k++) {
        int ts = t - 3 + k;
        if (ts >= 0) acc = fmaf(w[d * 4 + k], base[(size_t)ts * (2 * DI_)], acc);
    }
    float sg = 1.f / (1.f + __expf(-acc));
    xc[idx] = acc * sg;
}

// ---------------- selective scan + SiLU(z) gating (4-deep prefetch) ----------------
__global__ void scan_kernel(const float* __restrict__ xconv,
                            const float* __restrict__ dt,
                            const float* __restrict__ bcm,
                            const float* __restrict__ A_log,
                            const float* __restrict__ Dp,
                            const float* __restrict__ xz,
                            float* __restrict__ y) {
    int half = threadIdx.x >> 4;
    int lane = threadIdx.x & 15;
    int ch = blockIdx.x * (blockDim.x >> 4) + half;
    int b = ch / DI_;
    int d = ch % DI_;

    float a  = -expf(A_log[d * NS + lane]);
    float Dd = Dp[d];
    float h  = 0.f;

    const float* dtp = dt    + (size_t)b * LL * DI_ + d;
    const float* up  = xconv + (size_t)b * LL * DI_ + d;
    const float* bcp = bcm   + (size_t)b * LL * 32;
    const float* zp  = xz    + (size_t)b * LL * (2 * DI_) + DI_ + d;
    float*       yp  = y     + (size_t)b * LL * DI_ + d;

    float dtb[4], ub[4], Bb[4], Cb[4], zb[4];
    #pragma unroll
    for (int j = 0; j < 4; j++) {
        dtb[j] = dtp[(size_t)j * DI_];
        ub[j]  = up[(size_t)j * DI_];
        Bb[j]  = bcp[j * 32 + lane];
        Cb[j]  = bcp[j * 32 + 16 + lane];
        zb[j]  = (lane == 0) ? zp[(size_t)j * (2 * DI_)] : 0.f;
    }

    #pragma unroll 4
    for (int t = 0; t < LL; t++) {
        int j = t & 3;
        float dtv = dtb[j], uv = ub[j], Bn = Bb[j], Cn = Cb[j], zv = zb[j];
        int tn = t + 4;
        if (tn < LL) {
            dtb[j] = dtp[(size_t)tn * DI_];
            ub[j]  = up[(size_t)tn * DI_];
            Bb[j]  = bcp[tn * 32 + lane];
            Cb[j]  = bcp[tn * 32 + 16 + lane];
            zb[j]  = (lane == 0) ? zp[(size_t)tn * (2 * DI_)] : 0.f;
        }
        float dA = __expf(dtv * a);
        h = fmaf(h, dA, dtv * uv * Bn);
        float p = h * Cn;
        p += __shfl_xor_sync(0xffffffffu, p, 8);
        p += __shfl_xor_sync(0xffffffffu, p, 4);
        p += __shfl_xor_sync(0xffffffffu, p, 2);
        p += __shfl_xor_sync(0xffffffffu, p, 1);
        if (lane == 0) {
            float sz = zv / (1.f + __expf(-zv));
            yp[(size_t)t * DI_] = (p + uv * Dd) * sz;
        }
    }
}

// ---------------- launch ----------------
extern "C" void kernel_launch(void* const* d_in, const int* in_sizes, int n_in,
                              void* d_out, int out_size) {
    const float* x         = (const float*)d_in[0];
    const float* ln_g      = (const float*)d_in[1];
    const float* ln_b      = (const float*)d_in[2];
    const float* in_proj_w = (const float*)d_in[3];
    const float* conv_w    = (const float*)d_in[4];
    const float* conv_b    = (const float*)d_in[5];
    const float* dtin_w    = (const float*)d_in[6];
    const float* dtin_b    = (const float*)d_in[7];
    const float* dt_w      = (const float*)d_in[8];
    const float* dt_b      = (const float*)d_in[9];
    const float* B_w       = (const float*)d_in[10];
    const float* C_w       = (const float*)d_in[11];
    const float* A_log     = (const float*)d_in[12];
    const float* Dp        = (const float*)d_in[13];
    const float* out_w     = (const float*)d_in[14];
    float* out = (float*)d_out;

    float* s = nullptr;
    cudaGetSymbolAddress((void**)&s, g_scratch);
    float* xn     = s + OFF_XN;
    float* xz     = s + OFF_XZ;
    float* xconv  = s + OFF_XCONV;
    float* dtin   = s + OFF_DTIN;
    float* dt     = s + OFF_DT;
    float* bcm    = s + OFF_BCM;
    float* y      = s + OFF_Y;
    float* dtin_p = s + OFF_DTIN_P;
    float* bcm_p  = s + OFF_BCM_P;

    // 1) LayerNorm
    ln_kernel<<<MR, 256>>>(x, ln_g, ln_b, xn);

    // 2) xz = xn @ in_proj_w^T : (2048, 4096), K=1024
    hmma_nt<128, EPI_NONE, false, false><<<dim3(4096 / 128, MR / 128), 256>>>(
        xn, in_proj_w, nullptr, xz, MR, 4096, DM_, nullptr, nullptr, 0);

    // 3) causal conv + SiLU
    conv_silu_kernel<<<(BB * LL * DI_ + 255) / 256, 256>>>(xz, conv_w, conv_b, xconv);

    // 4) dt_in partials: xconv @ dtin_w^T : (2048, 64), K=2048, split-K=8
    hmma_nt<64, EPI_NONE, true, false><<<dim3(1, MR / 128, KSPLIT), 256>>>(
        xconv, dtin_w, nullptr, dtin_p, MR, DTR_, DI_, nullptr, nullptr, DI_ / KSPLIT);
    reduce_kernel<<<(MR * DTR_ + 255) / 256, 256>>>(dtin_p, dtin, dtin_b, MR * DTR_, DTR_);

    // 5) dt = softplus(dt_in @ dt_w^T + dt_b) : (2048, 2048), K=64
    hmma_nt<128, EPI_SOFTPLUS, false, false><<<dim3(DI_ / 128, MR / 128), 256>>>(
        dtin, dt_w, nullptr, dt, MR, DI_, DTR_, dt_b, nullptr, 0);

    // 6) [B | C] partials: xconv @ [B_w;C_w]^T : (2048, 32), K=2048, split-K=8
    hmma_nt<32, EPI_NONE, true, true><<<dim3(1, MR / 128, KSPLIT), 256>>>(
        xconv, B_w, C_w, bcm_p, MR, 32, DI_, nullptr, nullptr, DI_ / KSPLIT);
    reduce_kernel<<<(MR * 32 + 255) / 256, 256>>>(bcm_p, bcm, nullptr, MR * 32, 32);

    // 7) selective scan + SiLU(z) gating -> y
    scan_kernel<<<(BB * DI_) / 16, 256>>>(xconv, dt, bcm, A_log, Dp, xz, y);

    // 8) out = y @ out_w^T + residual(x) : (2048, 1024), K=2048
    hmma_nt<128, EPI_RES, false, false><<<dim3(DM_ / 128, MR / 128), 256>>>(
        y, out_w, nullptr, out, MR, DM_, DI_, nullptr, x, 0);
}

// round 5
// speedup vs baseline: 3.6734x; 1.1358x over previous
#include <cuda_runtime.h>
#include <cuda_fp16.h>
#include <math.h>
#include <stdint.h>

// ---------------- problem constants ----------------
#define BB   2
#define LL   1024
#define DM_  1024
#define DI_  2048
#define NS   16
#define MR   (BB * LL)        // 2048 rows
#define DTR_ 64
#define KSPLIT 8

// ---------------- fp32 scratch ----------------
#define OFF_XZ      0                       // (MR, 2*DI)
#define OFF_XCONV   (OFF_XZ + 8388608)      // (MR, DI) fp32 (scan u)
#define OFF_DT      (OFF_XCONV + 4194304)   // (MR, DI)
#define OFF_BCM     (OFF_DT + 4194304)      // (MR, 32)
#define OFF_DTIN_P  (OFF_BCM + 65536)       // (KSPLIT, MR, DTR)
#define OFF_BCM_P   (OFF_DTIN_P + 1048576)  // (KSPLIT, MR, 32)
#define SCRATCH_FLOATS (OFF_BCM_P + 524288)
__device__ float g_scratch[SCRATCH_FLOATS];

// ---------------- fp16 scratch ----------------
#define HXN     0                         // (MR, DM)          2097152
#define HXC     (HXN + 2097152)           // (MR, DI)          4194304
#define HY      (HXC + 4194304)           // (MR, DI)          4194304
#define HDTIN   (HY + 4194304)            // (MR, DTR)          131072
#define HWIN    (HDTIN + 131072)          // (4096, 1024)      4194304
#define HWDTIN  (HWIN + 4194304)          // (64, 2048)         131072
#define HWDT    (HWDTIN + 131072)         // (2048, 64)         131072
#define HWBC    (HWDT + 131072)           // (32, 2048)          65536
#define HWOUT   (HWBC + 65536)            // (1024, 2048)      2097152
#define SCRATCH_HALVES (HWOUT + 2097152)
__device__ __align__(256) __half g_hscratch[SCRATCH_HALVES];

// ---------------- helpers ----------------
__device__ __forceinline__ uint32_t pack_h2(float a, float b) {
    uint32_t p;
    asm("cvt.rn.f16x2.f32 %0, %1, %2;" : "=r"(p) : "f"(b), "f"(a));
    return p;
}
__device__ __forceinline__ uint32_t smem_u32(const void* p) {
    uint32_t a;
    asm("{ .reg .u64 t; cvta.to.shared.u64 t, %1; cvt.u32.u64 %0, t; }" : "=r"(a) : "l"(p));
    return a;
}
__device__ __forceinline__ void cp16(uint32_t dst, const void* src) {
    asm volatile("cp.async.cg.shared.global [%0], [%1], 16;" :: "r"(dst), "l"(src));
}

// ---------------- fp32 -> fp16 convert (n % 8 == 0) ----------------
__global__ void f2h_kernel(const float* __restrict__ in, __half* __restrict__ out, int n) {
    int i = (blockIdx.x * blockDim.x + threadIdx.x) * 8;
    if (i >= n) return;
    float4 a = *(const float4*)(in + i);
    float4 b = *(const float4*)(in + i + 4);
    uint4 u = { pack_h2(a.x, a.y), pack_h2(a.z, a.w), pack_h2(b.x, b.y), pack_h2(b.z, b.w) };
    *(uint4*)(out + i) = u;
}

// ---------------- LayerNorm (fp32 in -> fp16 out) ----------------
__global__ void ln_kernel(const float* __restrict__ x, const float* __restrict__ g,
                          const float* __restrict__ b, __half* __restrict__ o) {
    int row = blockIdx.x;
    int tid = threadIdx.x;
    const float4* xr = (const float4*)(x + (size_t)row * DM_);
    float4 v = xr[tid];
    float s  = v.x + v.y + v.z + v.w;
    float ss = v.x * v.x + v.y * v.y + v.z * v.z + v.w * v.w;
    #pragma unroll
    for (int off = 16; off > 0; off >>= 1) {
        s  += __shfl_xor_sync(0xffffffffu, s,  off);
        ss += __shfl_xor_sync(0xffffffffu, ss, off);
    }
    __shared__ float sh_s[8], sh_ss[8];
    int w = tid >> 5, l = tid & 31;
    if (l == 0) { sh_s[w] = s; sh_ss[w] = ss; }
    __syncthreads();
    if (w == 0) {
        s  = (l < 8) ? sh_s[l]  : 0.f;
        ss = (l < 8) ? sh_ss[l] : 0.f;
        #pragma unroll
        for (int off = 4; off > 0; off >>= 1) {
            s  += __shfl_xor_sync(0xffffffffu, s,  off);
            ss += __shfl_xor_sync(0xffffffffu, ss, off);
        }
        if (l == 0) { sh_s[0] = s; sh_ss[0] = ss; }
    }
    __syncthreads();
    float mu  = sh_s[0] * (1.0f / DM_);
    float var = sh_ss[0] * (1.0f / DM_) - mu * mu;
    float inv = rsqrtf(var + 1e-5f);
    float4 gg = ((const float4*)g)[tid];
    float4 bb = ((const float4*)b)[tid];
    float r0 = (v.x - mu) * inv * gg.x + bb.x;
    float r1 = (v.y - mu) * inv * gg.y + bb.y;
    float r2 = (v.z - mu) * inv * gg.z + bb.z;
    float r3 = (v.w - mu) * inv * gg.w + bb.w;
    uint2 u = { pack_h2(r0, r1), pack_h2(r2, r3) };
    *(uint2*)(o + (size_t)row * DM_ + tid * 4) = u;
}

// ---------------- fp16 tensor-core GEMM (cp.async 3-stage): C = A * B^T ----------------
// A (M,K) fp16 row-major, B (N,K) fp16 row-major, C fp32.
// BM=128, BK=32 halves (64B rows, 16 words). Swizzle: word = r*16 + ((ch^((r>>1)&3))<<2)+off.
enum { EPI_NONE = 0, EPI_SOFTPLUS = 2, EPI_RES = 3 };

template<int BN, int EPI, bool SPLITK>
__global__ void __launch_bounds__(256)
hgemm(const __half* __restrict__ A, const __half* __restrict__ Bw,
      float* __restrict__ C, int M, int N, int K,
      const float* __restrict__ bias, const float* __restrict__ res,
      int ksplit_len) {
    constexpr int BK = 32;
    constexpr int STG = 3;
    constexpr int ROWS = 128 + BN;
    constexpr int WN = BN / 4;
    constexpr int MI = 4;                 // 64 rows per warp / 16
    constexpr int NI = WN / 8;
    constexpr int BCH = BN * 4;           // 16B chunks in B tile

    __shared__ uint32_t sm[STG * ROWS * 16];

    const int tid  = threadIdx.x;
    const int warp = tid >> 5, lane = tid & 31;
    const int g  = lane >> 2, tg = lane & 3;
    const int wm = (warp & 1) * 64;
    const int wn = (warp >> 1) * WN;
    const int bm = blockIdx.y * 128;
    const int bn = blockIdx.x * BN;
    const int swz = (g >> 1) & 3;
    const uint32_t smb = smem_u32(sm);

    int k_begin = 0, k_len = K;
    if (SPLITK) { k_begin = blockIdx.z * ksplit_len; k_len = ksplit_len; }
    const int NT = k_len / BK;

    const __half* Ag = A + (size_t)bm * K + k_begin;
    const __half* Bg = Bw + (size_t)bn * K + k_begin;

    auto load_tile = [&](int st, int kt) {
        const uint32_t sb = smb + st * (ROWS * 64);
        const int k0 = kt * BK;
        #pragma unroll
        for (int i = 0; i < 2; i++) {                      // A: 512 chunks
            int idx = tid + i * 256;
            int r = idx >> 2, ch = idx & 3;
            uint32_t dst = sb + (r * 16 + ((ch ^ ((r >> 1) & 3)) << 2)) * 4;
            cp16(dst, Ag + (size_t)r * K + k0 + ch * 8);
        }
        #pragma unroll
        for (int i = 0; i < (BCH + 255) / 256; i++) {      // B tile
            int idx = tid + i * 256;
            if (BCH % 256 == 0 || idx < BCH) {
                int r = idx >> 2, ch = idx & 3;
                uint32_t dst = sb + ((128 + r) * 16 + ((ch ^ ((r >> 1) & 3)) << 2)) * 4;
                cp16(dst, Bg + (size_t)r * K + k0 + ch * 8);
            }
        }
    };

    int rowA[MI], rowB[NI];
    #pragma unroll
    for (int mi = 0; mi < MI; mi++) rowA[mi] = (wm + mi * 16 + g) * 16;
    #pragma unroll
    for (int ni = 0; ni < NI; ni++) rowB[ni] = (128 + wn + ni * 8 + g) * 16;

    float c[MI][NI][4];
    #pragma unroll
    for (int mi = 0; mi < MI; mi++)
        #pragma unroll
        for (int ni = 0; ni < NI; ni++)
            #pragma unroll
            for (int q = 0; q < 4; q++) c[mi][ni][q] = 0.f;

    // prologue: 2 tiles in flight
    if (0 < NT) load_tile(0, 0);
    asm volatile("cp.async.commit_group;" ::: "memory");
    if (1 < NT) load_tile(1, 1);
    asm volatile("cp.async.commit_group;" ::: "memory");

    for (int it = 0; it < NT; it++) {
        const int st = it % 3;
        asm volatile("cp.async.wait_group 1;" ::: "memory");
        __syncthreads();
        if (it + 2 < NT) load_tile((it + 2) % 3, it + 2);
        asm volatile("cp.async.commit_group;" ::: "memory");

        const uint32_t* smt = sm + st * (ROWS * 16);
        #pragma unroll
        for (int kk = 0; kk < 2; kk++) {
            const int c0 = (((2 * kk) ^ swz) << 2) + tg;
            const int c1 = (((2 * kk + 1) ^ swz) << 2) + tg;
            uint32_t af[MI][4], bf[NI][2];
            #pragma unroll
            for (int mi = 0; mi < MI; mi++) {
                af[mi][0] = smt[rowA[mi]       + c0];
                af[mi][1] = smt[rowA[mi] + 128 + c0];
                af[mi][2] = smt[rowA[mi]       + c1];
                af[mi][3] = smt[rowA[mi] + 128 + c1];
            }
            #pragma unroll
            for (int ni = 0; ni < NI; ni++) {
                bf[ni][0] = smt[rowB[ni] + c0];
                bf[ni][1] = smt[rowB[ni] + c1];
            }
            #pragma unroll
            for (int mi = 0; mi < MI; mi++)
                #pragma unroll
                for (int ni = 0; ni < NI; ni++) {
                    asm volatile(
                        "mma.sync.aligned.m16n8k16.row.col.f32.f16.f16.f32 "
                        "{%0,%1,%2,%3}, {%4,%5,%6,%7}, {%8,%9}, {%0,%1,%2,%3};"
                        : "+f"(c[mi][ni][0]), "+f"(c[mi][ni][1]),
                          "+f"(c[mi][ni][2]), "+f"(c[mi][ni][3])
                        : "r"(af[mi][0]), "r"(af[mi][1]), "r"(af[mi][2]), "r"(af[mi][3]),
                          "r"(bf[ni][0]), "r"(bf[ni][1]));
                }
        }
        __syncthreads();
    }

    float* Cb = C;
    if (SPLITK) Cb += (size_t)blockIdx.z * (size_t)M * N;
    #pragma unroll
    for (int mi = 0; mi < MI; mi++) {
        #pragma unroll
        for (int ni = 0; ni < NI; ni++) {
            int coln = bn + wn + ni * 8 + tg * 2;
            #pragma unroll
            for (int h = 0; h < 2; h++) {
                int row = bm + wm + mi * 16 + g + h * 8;
                float v0 = c[mi][ni][2 * h + 0];
                float v1 = c[mi][ni][2 * h + 1];
                if (EPI == EPI_SOFTPLUS) {
                    v0 += bias[coln]; v1 += bias[coln + 1];
                    v0 = (v0 > 20.f) ? v0 : log1pf(expf(v0));
                    v1 = (v1 > 20.f) ? v1 : log1pf(expf(v1));
                } else if (EPI == EPI_RES) {
                    float2 rr = *(const float2*)&res[(size_t)row * N + coln];
                    v0 += rr.x; v1 += rr.y;
                }
                float2 out = { v0, v1 };
                *(float2*)&Cb[(size_t)row * N + coln] = out;
            }
        }
    }
}

// ---------------- split-K reduce ----------------
template<bool HALF_OUT>
__global__ void reduce_kernel(const float* __restrict__ part, void* __restrict__ out,
                              const float* __restrict__ bias, int MN, int Ncols) {
    int i = blockIdx.x * blockDim.x + threadIdx.x;
    if (i >= MN) return;
    float s = bias ? bias[i % Ncols] : 0.f;
    #pragma unroll
    for (int p = 0; p < KSPLIT; p++) s += part[(size_t)p * MN + i];
    if (HALF_OUT) ((__half*)out)[i] = __float2half(s);
    else          ((float*)out)[i] = s;
}

// ---------------- causal depthwise conv (k=4) + SiLU (dual fp32/fp16 out) ----------------
__global__ void conv_silu_kernel(const float* __restrict__ xz,
                                 const float* __restrict__ w,
                                 const float* __restrict__ cb,
                                 float* __restrict__ xc32,
                                 __half* __restrict__ xc16) {
    int idx = blockIdx.x * blockDim.x + threadIdx.x;
    if (idx >= BB * LL * DI_) return;
    int d = idx % DI_;
    int t = (idx / DI_) % LL;
    int b = idx / (DI_ * LL);
    const float* base = xz + (size_t)b * LL * (2 * DI_) + d;
    float acc = cb[d];
    #pragma unroll
    for (int k = 0; k < 4; k++) {
        int ts = t - 3 + k;
        if (ts >= 0) acc = fmaf(w[d * 4 + k], base[(size_t)ts * (2 * DI_)], acc);
    }
    float sg = 1.f / (1.f + __expf(-acc));
    float v = acc * sg;
    xc32[idx] = v;
    xc16[idx] = __float2half(v);
}

// ---------------- selective scan + SiLU(z) gating (fp16 y out) ----------------
__global__ void scan_kernel(const float* __restrict__ xconv,
                            const float* __restrict__ dt,
                            const float* __restrict__ bcm,
                            const float* __restrict__ A_log,
                            const float* __restrict__ Dp,
                            const float* __restrict__ xz,
                            __half* __restrict__ y) {
    int half = threadIdx.x >> 4;
    int lane = threadIdx.x & 15;
    int ch = blockIdx.x * (blockDim.x >> 4) + half;
    int b = ch / DI_;
    int d = ch % DI_;

    float a  = -expf(A_log[d * NS + lane]);
    float Dd = Dp[d];
    float h  = 0.f;

    const float* dtp = dt    + (size_t)b * LL * DI_ + d;
    const float* up  = xconv + (size_t)b * LL * DI_ + d;
    const float* bcp = bcm   + (size_t)b * LL * 32;
    const float* zp  = xz    + (size_t)b * LL * (2 * DI_) + DI_ + d;
    __half*      yp  = y     + (size_t)b * LL * DI_ + d;

    float dtb[4], ub[4], Bb[4], Cb[4], zb[4];
    #pragma unroll
    for (int j = 0; j < 4; j++) {
        dtb[j] = dtp[(size_t)j * DI_];
        ub[j]  = up[(size_t)j * DI_];
        Bb[j]  = bcp[j * 32 + lane];
        Cb[j]  = bcp[j * 32 + 16 + lane];
        zb[j]  = (lane == 0) ? zp[(size_t)j * (2 * DI_)] : 0.f;
    }

    #pragma unroll 4
    for (int t = 0; t < LL; t++) {
        int j = t & 3;
        float dtv = dtb[j], uv = ub[j], Bn = Bb[j], Cn = Cb[j], zv = zb[j];
        int tn = t + 4;
        if (tn < LL) {
            dtb[j] = dtp[(size_t)tn * DI_];
            ub[j]  = up[(size_t)tn * DI_];
            Bb[j]  = bcp[tn * 32 + lane];
            Cb[j]  = bcp[tn * 32 + 16 + lane];
            zb[j]  = (lane == 0) ? zp[(size_t)tn * (2 * DI_)] : 0.f;
        }
        float dA = __expf(dtv * a);
        h = fmaf(h, dA, dtv * uv * Bn);
        float p = h * Cn;
        p += __shfl_xor_sync(0xffffffffu, p, 8);
        p += __shfl_xor_sync(0xffffffffu, p, 4);
        p += __shfl_xor_sync(0xffffffffu, p, 2);
        p += __shfl_xor_sync(0xffffffffu, p, 1);
        if (lane == 0) {
            float sz = zv / (1.f + __expf(-zv));
            yp[(size_t)t * DI_] = __float2half((p + uv * Dd) * sz);
        }
    }
}

// ---------------- launch ----------------
extern "C" void kernel_launch(void* const* d_in, const int* in_sizes, int n_in,
                              void* d_out, int out_size) {
    const float* x         = (const float*)d_in[0];
    const float* ln_g      = (const float*)d_in[1];
    const float* ln_b      = (const float*)d_in[2];
    const float* in_proj_w = (const float*)d_in[3];
    const float* conv_w    = (const float*)d_in[4];
    const float* conv_b    = (const float*)d_in[5];
    const float* dtin_w    = (const float*)d_in[6];
    const float* dtin_b    = (const float*)d_in[7];
    const float* dt_w      = (const float*)d_in[8];
    const float* dt_b      = (const float*)d_in[9];
    const float* B_w       = (const float*)d_in[10];
    const float* C_w       = (const float*)d_in[11];
    const float* A_log     = (const float*)d_in[12];
    const float* Dp        = (const float*)d_in[13];
    const float* out_w     = (const float*)d_in[14];
    float* out = (float*)d_out;

    float* s = nullptr;
    cudaGetSymbolAddress((void**)&s, g_scratch);
    __half* hs = nullptr;
    cudaGetSymbolAddress((void**)&hs, g_hscratch);

    float* xz     = s + OFF_XZ;
    float* xconv  = s + OFF_XCONV;
    float* dt     = s + OFF_DT;
    float* bcm    = s + OFF_BCM;
    float* dtin_p = s + OFF_DTIN_P;
    float* bcm_p  = s + OFF_BCM_P;

    __half* xn16    = hs + HXN;
    __half* xc16    = hs + HXC;
    __half* y16     = hs + HY;
    __half* dtin16  = hs + HDTIN;
    __half* win16   = hs + HWIN;
    __half* wdtin16 = hs + HWDTIN;
    __half* wdt16   = hs + HWDT;
    __half* wbc16   = hs + HWBC;
    __half* wout16  = hs + HWOUT;

    // 0) convert weights to fp16 (bandwidth-trivial)
    f2h_kernel<<<(4194304 / 8 + 255) / 256, 256>>>(in_proj_w, win16, 4194304);
    f2h_kernel<<<(131072 / 8 + 255) / 256, 256>>>(dtin_w, wdtin16, 131072);
    f2h_kernel<<<(131072 / 8 + 255) / 256, 256>>>(dt_w, wdt16, 131072);
    f2h_kernel<<<(32768 / 8 + 255) / 256, 256>>>(B_w, wbc16, 32768);
    f2h_kernel<<<(32768 / 8 + 255) / 256, 256>>>(C_w, wbc16 + 32768, 32768);
    f2h_kernel<<<(2097152 / 8 + 255) / 256, 256>>>(out_w, wout16, 2097152);

    // 1) LayerNorm -> fp16
    ln_kernel<<<MR, 256>>>(x, ln_g, ln_b, xn16);

    // 2) xz = xn @ in_proj_w^T : (2048, 4096), K=1024
    hgemm<128, EPI_NONE, false><<<dim3(4096 / 128, MR / 128), 256>>>(
        xn16, win16, xz, MR, 4096, DM_, nullptr, nullptr, 0);

    // 3) causal conv + SiLU -> fp32 + fp16
    conv_silu_kernel<<<(BB * LL * DI_ + 255) / 256, 256>>>(xz, conv_w, conv_b, xconv, xc16);

    // 4) dt_in partials: xc @ dtin_w^T : (2048, 64), K=2048, split-K=8 -> fp16 dtin
    hgemm<64, EPI_NONE, true><<<dim3(1, MR / 128, KSPLIT), 256>>>(
        xc16, wdtin16, dtin_p, MR, DTR_, DI_, nullptr, nullptr, DI_ / KSPLIT);
    reduce_kernel<true><<<(MR * DTR_ + 255) / 256, 256>>>(dtin_p, dtin16, dtin_b, MR * DTR_, DTR_);

    // 5) dt = softplus(dtin @ dt_w^T + dt_b) : (2048, 2048), K=64
    hgemm<128, EPI_SOFTPLUS, false><<<dim3(DI_ / 128, MR / 128), 256>>>(
        dtin16, wdt16, dt, MR, DI_, DTR_, dt_b, nullptr, 0);

    // 6) [B|C] partials: xc @ [B_w;C_w]^T : (2048, 32), K=2048, split-K=8
    hgemm<32, EPI_NONE, true><<<dim3(1, MR / 128, KSPLIT), 256>>>(
        xc16, wbc16, bcm_p, MR, 32, DI_, nullptr, nullptr, DI_ / KSPLIT);
    reduce_kernel<false><<<(MR * 32 + 255) / 256, 256>>>(bcm_p, bcm, nullptr, MR * 32, 32);

    // 7) selective scan + SiLU(z) gating -> fp16 y
    scan_kernel<<<(BB * DI_) / 16, 256>>>(xconv, dt, bcm, A_log, Dp, xz, y16);

    // 8) out = y @ out_w^T + residual(x) : (2048, 1024), K=2048
    hgemm<128, EPI_RES, false><<<dim3(DM_ / 128, MR / 128), 256>>>(
        y16, wout16, out, MR, DM_, DI_, nullptr, x, 0);
}

// round 6
// speedup vs baseline: 3.8018x; 1.0350x over previous
#include <cuda_runtime.h>
#include <cuda_fp16.h>
#include <math.h>
#include <stdint.h>

// ---------------- problem constants ----------------
#define BB   2
#define LL   1024
#define DM_  1024
#define DI_  2048
#define NS   16
#define MR   (BB * LL)        // 2048 rows
#define DTR_ 64
#define KSPLIT 8

// ---------------- fp32 scratch ----------------
#define OFF_XZ      0                       // (MR, 2*DI)
#define OFF_XCONV   (OFF_XZ + 8388608)      // (MR, DI) fp32 (scan u)
#define OFF_DT      (OFF_XCONV + 4194304)   // (MR, DI)
#define OFF_BCM     (OFF_DT + 4194304)      // (MR, 32)
#define OFF_DTIN_P  (OFF_BCM + 65536)       // (KSPLIT, MR, DTR)
#define OFF_BCM_P   (OFF_DTIN_P + 1048576)  // (KSPLIT, MR, 32)
#define SCRATCH_FLOATS (OFF_BCM_P + 524288)
__device__ float g_scratch[SCRATCH_FLOATS];

// ---------------- fp16 scratch ----------------
#define HXN     0                         // (MR, DM)          2097152
#define HXC     (HXN + 2097152)           // (MR, DI)          4194304
#define HY      (HXC + 4194304)           // (MR, DI)          4194304
#define HDTIN   (HY + 4194304)            // (MR, DTR)          131072
#define HWIN    (HDTIN + 131072)          // (4096, 1024)      4194304
#define HWDTIN  (HWIN + 4194304)          // (64, 2048)         131072
#define HWDT    (HWDTIN + 131072)         // (2048, 64)         131072
#define HWBC    (HWDT + 131072)           // (32, 2048)          65536
#define HWOUT   (HWBC + 65536)            // (1024, 2048)      2097152
#define SCRATCH_HALVES (HWOUT + 2097152)
__device__ __align__(256) __half g_hscratch[SCRATCH_HALVES];

// ---------------- helpers ----------------
__device__ __forceinline__ uint32_t pack_h2(float a, float b) {
    uint32_t p;
    asm("cvt.rn.f16x2.f32 %0, %1, %2;" : "=r"(p) : "f"(b), "f"(a));
    return p;
}
__device__ __forceinline__ uint32_t smem_u32(const void* p) {
    uint32_t a;
    asm("{ .reg .u64 t; cvta.to.shared.u64 t, %1; cvt.u32.u64 %0, t; }" : "=r"(a) : "l"(p));
    return a;
}
__device__ __forceinline__ void cp16(uint32_t dst, const void* src) {
    asm volatile("cp.async.cg.shared.global [%0], [%1], 16;" :: "r"(dst), "l"(src));
}
__device__ __forceinline__ void ldm_x4(uint32_t& r0, uint32_t& r1, uint32_t& r2, uint32_t& r3,
                                       uint32_t addr) {
    asm volatile("ldmatrix.sync.aligned.m8n8.x4.shared.b16 {%0,%1,%2,%3}, [%4];"
                 : "=r"(r0), "=r"(r1), "=r"(r2), "=r"(r3) : "r"(addr));
}
__device__ __forceinline__ void ldm_x2(uint32_t& r0, uint32_t& r1, uint32_t addr) {
    asm volatile("ldmatrix.sync.aligned.m8n8.x2.shared.b16 {%0,%1}, [%2];"
                 : "=r"(r0), "=r"(r1) : "r"(addr));
}

// ---------------- fused fp32 -> fp16 weight convert (1 launch) ----------------
// segments (floats): win 4194304 | wdtin 131072 | wdt 131072 | B_w 32768 | C_w 32768 | wout 2097152
#define F2H_TOTAL 6619136
__global__ void f2h_all(const float* w0, const float* w1, const float* w2,
                        const float* w3, const float* w4, const float* w5,
                        __half* hbase) {
    int i = (blockIdx.x * blockDim.x + threadIdx.x) * 8;
    if (i >= F2H_TOTAL) return;
    const float* s; __half* d; int off;
    if (i < 4194304)      { s = w0; d = hbase + HWIN;           off = i; }
    else if (i < 4325376) { s = w1; d = hbase + HWDTIN;         off = i - 4194304; }
    else if (i < 4456448) { s = w2; d = hbase + HWDT;           off = i - 4325376; }
    else if (i < 4489216) { s = w3; d = hbase + HWBC;           off = i - 4456448; }
    else if (i < 4521984) { s = w4; d = hbase + HWBC + 32768;   off = i - 4489216; }
    else                  { s = w5; d = hbase + HWOUT;          off = i - 4521984; }
    float4 a = *(const float4*)(s + off);
    float4 b = *(const float4*)(s + off + 4);
    uint4 u = { pack_h2(a.x, a.y), pack_h2(a.z, a.w), pack_h2(b.x, b.y), pack_h2(b.z, b.w) };
    *(uint4*)(d + off) = u;
}

// ---------------- LayerNorm (fp32 in -> fp16 out) ----------------
__global__ void ln_kernel(const float* __restrict__ x, const float* __restrict__ g,
                          const float* __restrict__ b, __half* __restrict__ o) {
    int row = blockIdx.x;
    int tid = threadIdx.x;
    const float4* xr = (const float4*)(x + (size_t)row * DM_);
    float4 v = xr[tid];
    float s  = v.x + v.y + v.z + v.w;
    float ss = v.x * v.x + v.y * v.y + v.z * v.z + v.w * v.w;
    #pragma unroll
    for (int off = 16; off > 0; off >>= 1) {
        s  += __shfl_xor_sync(0xffffffffu, s,  off);
        ss += __shfl_xor_sync(0xffffffffu, ss, off);
    }
    __shared__ float sh_s[8], sh_ss[8];
    int w = tid >> 5, l = tid & 31;
    if (l == 0) { sh_s[w] = s; sh_ss[w] = ss; }
    __syncthreads();
    if (w == 0) {
        s  = (l < 8) ? sh_s[l]  : 0.f;
        ss = (l < 8) ? sh_ss[l] : 0.f;
        #pragma unroll
        for (int off = 4; off > 0; off >>= 1) {
            s  += __shfl_xor_sync(0xffffffffu, s,  off);
            ss += __shfl_xor_sync(0xffffffffu, ss, off);
        }
        if (l == 0) { sh_s[0] = s; sh_ss[0] = ss; }
    }
    __syncthreads();
    float mu  = sh_s[0] * (1.0f / DM_);
    float var = sh_ss[0] * (1.0f / DM_) - mu * mu;
    float inv = rsqrtf(var + 1e-5f);
    float4 gg = ((const float4*)g)[tid];
    float4 bb = ((const float4*)b)[tid];
    float r0 = (v.x - mu) * inv * gg.x + bb.x;
    float r1 = (v.y - mu) * inv * gg.y + bb.y;
    float r2 = (v.z - mu) * inv * gg.z + bb.z;
    float r3 = (v.w - mu) * inv * gg.w + bb.w;
    uint2 u = { pack_h2(r0, r1), pack_h2(r2, r3) };
    *(uint2*)(o + (size_t)row * DM_ + tid * 4) = u;
}

// ---------------- fp16 tensor-core GEMM (cp.async 3-stage + ldmatrix) ----------------
// A (M,K) fp16 row-major, B (N,K) fp16 row-major, C (M,N) fp32 = A*B^T.
// BM=128, BK=32 halves (64B rows = 4 x 16B chunks). Swizzle: chunk ^= (r>>1)&3.
enum { EPI_NONE = 0, EPI_SOFTPLUS = 2, EPI_RES = 3 };

template<int BN, int EPI, bool SPLITK>
__global__ void __launch_bounds__(256)
hgemm(const __half* __restrict__ A, const __half* __restrict__ Bw,
      float* __restrict__ C, int M, int N, int K,
      const float* __restrict__ bias, const float* __restrict__ res,
      int ksplit_len) {
    constexpr int BK = 32;
    constexpr int STG = 3;
    constexpr int ROWS = 128 + BN;
    constexpr int WN = BN / 4;
    constexpr int MI = 4;
    constexpr int NI = WN / 8;            // 4 / 2 / 1
    constexpr int BCH = BN * 4;

    __shared__ uint32_t sm[STG * ROWS * 16];

    const int tid  = threadIdx.x;
    const int warp = tid >> 5, lane = tid & 31;
    const int g  = lane >> 2, tg = lane & 3;
    const int wm = (warp & 1) * 64;
    const int wn = (warp >> 1) * WN;
    const int bm = blockIdx.y * 128;
    const int bn = blockIdx.x * BN;
    const uint32_t smb = smem_u32(sm);

    // per-lane ldmatrix addressing
    const int lrow   = lane & 7;
    const int a_radd = ((lane >> 3) & 1) * 8;   // +8 rows for mats 1,3
    const int a_chad = (lane >> 4) & 1;         // +1 chunk for mats 2,3
    const int b_radd = ((lane >> 4) & 1) * 8;   // +8 rows for mats 2,3
    const int b_chad = (lane >> 3) & 1;         // +1 chunk for mats 1,3

    int k_begin = 0, k_len = K;
    if (SPLITK) { k_begin = blockIdx.z * ksplit_len; k_len = ksplit_len; }
    const int NT = k_len / BK;

    const __half* Ag = A + (size_t)bm * K + k_begin;
    const __half* Bg = Bw + (size_t)bn * K + k_begin;

    auto load_tile = [&](int st, int kt) {
        const uint32_t sb = smb + st * (ROWS * 64);
        const int k0 = kt * BK;
        #pragma unroll
        for (int i = 0; i < 2; i++) {
            int idx = tid + i * 256;
            int r = idx >> 2, ch = idx & 3;
            uint32_t dst = sb + (r * 16 + ((ch ^ ((r >> 1) & 3)) << 2)) * 4;
            cp16(dst, Ag + (size_t)r * K + k0 + ch * 8);
        }
        #pragma unroll
        for (int i = 0; i < (BCH + 255) / 256; i++) {
            int idx = tid + i * 256;
            if (BCH % 256 == 0 || idx < BCH) {
                int r = idx >> 2, ch = idx & 3;
                uint32_t dst = sb + ((128 + r) * 16 + ((ch ^ ((r >> 1) & 3)) << 2)) * 4;
                cp16(dst, Bg + (size_t)r * K + k0 + ch * 8);
            }
        }
    };

    float c[MI][NI][4];
    #pragma unroll
    for (int mi = 0; mi < MI; mi++)
        #pragma unroll
        for (int ni = 0; ni < NI; ni++)
            #pragma unroll
            for (int q = 0; q < 4; q++) c[mi][ni][q] = 0.f;

    if (0 < NT) load_tile(0, 0);
    asm volatile("cp.async.commit_group;" ::: "memory");
    if (1 < NT) load_tile(1, 1);
    asm volatile("cp.async.commit_group;" ::: "memory");

    for (int it = 0; it < NT; it++) {
        const int st = it % 3;
        asm volatile("cp.async.wait_group 1;" ::: "memory");
        __syncthreads();
        if (it + 2 < NT) load_tile((it + 2) % 3, it + 2);
        asm volatile("cp.async.commit_group;" ::: "memory");

        const uint32_t smt = smb + st * (ROWS * 64);
        #pragma unroll
        for (int kk = 0; kk < 2; kk++) {
            uint32_t af[MI][4], bf[NI][2];
            #pragma unroll
            for (int mi = 0; mi < MI; mi++) {
                int r  = wm + mi * 16 + lrow + a_radd;
                int ch = 2 * kk + a_chad;
                uint32_t addr = smt + (r * 16 + ((ch ^ ((r >> 1) & 3)) << 2)) * 4;
                ldm_x4(af[mi][0], af[mi][1], af[mi][2], af[mi][3], addr);
            }
            if (NI == 1) {
                int r  = 128 + wn + lrow + ((lane >> 3) & 1) * 0;   // lanes 0-15 used
                int ch = 2 * kk + b_chad;                            // chunk toggles by lane bit3
                // x2: mats (n0-7, ch 2kk) and (n0-7, ch 2kk+1)
                int rr = 128 + wn + lrow;
                uint32_t addr = smt + (rr * 16 + (((2 * kk + ((lane >> 3) & 1)) ^ ((rr >> 1) & 3)) << 2)) * 4;
                (void)r; (void)ch;
                ldm_x2(bf[0][0], bf[0][1], addr);
            } else {
                #pragma unroll
                for (int ng = 0; ng < NI / 2; ng++) {
                    int r  = 128 + wn + ng * 16 + lrow + b_radd;
                    int ch = 2 * kk + b_chad;
                    uint32_t addr = smt + (r * 16 + ((ch ^ ((r >> 1) & 3)) << 2)) * 4;
                    uint32_t r0, r1, r2, r3;
                    ldm_x4(r0, r1, r2, r3, addr);
                    bf[2 * ng][0] = r0; bf[2 * ng][1] = r1;
                    bf[2 * ng + 1][0] = r2; bf[2 * ng + 1][1] = r3;
                }
            }
            #pragma unroll
            for (int mi = 0; mi < MI; mi++)
                #pragma unroll
                for (int ni = 0; ni < NI; ni++) {
                    asm volatile(
                        "mma.sync.aligned.m16n8k16.row.col.f32.f16.f16.f32 "
                        "{%0,%1,%2,%3}, {%4,%5,%6,%7}, {%8,%9}, {%0,%1,%2,%3};"
                        : "+f"(c[mi][ni][0]), "+f"(c[mi][ni][1]),
                          "+f"(c[mi][ni][2]), "+f"(c[mi][ni][3])
                        : "r"(af[mi][0]), "r"(af[mi][1]), "r"(af[mi][2]), "r"(af[mi][3]),
                          "r"(bf[ni][0]), "r"(bf[ni][1]));
                }
        }
        __syncthreads();
    }

    float* Cb = C;
    if (SPLITK) Cb += (size_t)blockIdx.z * (size_t)M * N;
    #pragma unroll
    for (int mi = 0; mi < MI; mi++) {
        #pragma unroll
        for (int ni = 0; ni < NI; ni++) {
            int coln = bn + wn + ni * 8 + tg * 2;
            #pragma unroll
            for (int h = 0; h < 2; h++) {
                int row = bm + wm + mi * 16 + g + h * 8;
                float v0 = c[mi][ni][2 * h + 0];
                float v1 = c[mi][ni][2 * h + 1];
                if (EPI == EPI_SOFTPLUS) {
                    v0 += bias[coln]; v1 += bias[coln + 1];
                    v0 = (v0 > 20.f) ? v0 : log1pf(expf(v0));
                    v1 = (v1 > 20.f) ? v1 : log1pf(expf(v1));
                } else if (EPI == EPI_RES) {
                    float2 rr = *(const float2*)&res[(size_t)row * N + coln];
                    v0 += rr.x; v1 += rr.y;
                }
                float2 out = { v0, v1 };
                *(float2*)&Cb[(size_t)row * N + coln] = out;
            }
        }
    }
}

// ---------------- split-K reduce ----------------
template<bool HALF_OUT>
__global__ void reduce_kernel(const float* __restrict__ part, void* __restrict__ out,
                              const float* __restrict__ bias, int MN, int Ncols) {
    int i = blockIdx.x * blockDim.x + threadIdx.x;
    if (i >= MN) return;
    float s = bias ? bias[i % Ncols] : 0.f;
    #pragma unroll
    for (int p = 0; p < KSPLIT; p++) s += part[(size_t)p * MN + i];
    if (HALF_OUT) ((__half*)out)[i] = __float2half(s);
    else          ((float*)out)[i] = s;
}

// ---------------- causal depthwise conv (k=4) + SiLU (dual out) ----------------
__global__ void conv_silu_kernel(const float* __restrict__ xz,
                                 const float* __restrict__ w,
                                 const float* __restrict__ cb,
                                 float* __restrict__ xc32,
                                 __half* __restrict__ xc16) {
    int idx = blockIdx.x * blockDim.x + threadIdx.x;
    if (idx >= BB * LL * DI_) return;
    int d = idx % DI_;
    int t = (idx / DI_) % LL;
    int b = idx / (DI_ * LL);
    const float* base = xz + (size_t)b * LL * (2 * DI_) + d;
    float acc = cb[d];
    #pragma unroll
    for (int k = 0; k < 4; k++) {
        int ts = t - 3 + k;
        if (ts >= 0) acc = fmaf(w[d * 4 + k], base[(size_t)ts * (2 * DI_)], acc);
    }
    float sg = 1.f / (1.f + __expf(-acc));
    float v = acc * sg;
    xc32[idx] = v;
    xc16[idx] = __float2half(v);
}

// ---------------- selective scan + SiLU(z) gating (fp16 y out) ----------------
__global__ void scan_kernel(const float* __restrict__ xconv,
                            const float* __restrict__ dt,
                            const float* __restrict__ bcm,
                            const float* __restrict__ A_log,
                            const float* __restrict__ Dp,
                            const float* __restrict__ xz,
                            __half* __restrict__ y) {
    int half = threadIdx.x >> 4;
    int lane = threadIdx.x & 15;
    int ch = blockIdx.x * (blockDim.x >> 4) + half;
    int b = ch / DI_;
    int d = ch % DI_;

    float a  = -expf(A_log[d * NS + lane]);
    float Dd = Dp[d];
    float h  = 0.f;

    const float* dtp = dt    + (size_t)b * LL * DI_ + d;
    const float* up  = xconv + (size_t)b * LL * DI_ + d;
    const float* bcp = bcm   + (size_t)b * LL * 32;
    const float* zp  = xz    + (size_t)b * LL * (2 * DI_) + DI_ + d;
    __half*      yp  = y     + (size_t)b * LL * DI_ + d;

    float dtb[4], ub[4], Bb[4], Cb[4], zb[4];
    #pragma unroll
    for (int j = 0; j < 4; j++) {
        dtb[j] = dtp[(size_t)j * DI_];
        ub[j]  = up[(size_t)j * DI_];
        Bb[j]  = bcp[j * 32 + lane];
        Cb[j]  = bcp[j * 32 + 16 + lane];
        zb[j]  = (lane == 0) ? zp[(size_t)j * (2 * DI_)] : 0.f;
    }

    #pragma unroll 4
    for (int t = 0; t < LL; t++) {
        int j = t & 3;
        float dtv = dtb[j], uv = ub[j], Bn = Bb[j], Cn = Cb[j], zv = zb[j];
        int tn = t + 4;
        if (tn < LL) {
            dtb[j] = dtp[(size_t)tn * DI_];
            ub[j]  = up[(size_t)tn * DI_];
            Bb[j]  = bcp[tn * 32 + lane];
            Cb[j]  = bcp[tn * 32 + 16 + lane];
            zb[j]  = (lane == 0) ? zp[(size_t)tn * (2 * DI_)] : 0.f;
        }
        float dA = __expf(dtv * a);
        h = fmaf(h, dA, dtv * uv * Bn);
        float p = h * Cn;
        p += __shfl_xor_sync(0xffffffffu, p, 8);
        p += __shfl_xor_sync(0xffffffffu, p, 4);
        p += __shfl_xor_sync(0xffffffffu, p, 2);
        p += __shfl_xor_sync(0xffffffffu, p, 1);
        if (lane == 0) {
            float sz = zv / (1.f + __expf(-zv));
            yp[(size_t)t * DI_] = __float2half((p + uv * Dd) * sz);
        }
    }
}

// ---------------- launch ----------------
extern "C" void kernel_launch(void* const* d_in, const int* in_sizes, int n_in,
                              void* d_out, int out_size) {
    const float* x         = (const float*)d_in[0];
    const float* ln_g      = (const float*)d_in[1];
    const float* ln_b      = (const float*)d_in[2];
    const float* in_proj_w = (const float*)d_in[3];
    const float* conv_w    = (const float*)d_in[4];
    const float* conv_b    = (const float*)d_in[5];
    const float* dtin_w    = (const float*)d_in[6];
    const float* dtin_b    = (const float*)d_in[7];
    const float* dt_w      = (const float*)d_in[8];
    const float* dt_b      = (const float*)d_in[9];
    const float* B_w       = (const float*)d_in[10];
    const float* C_w       = (const float*)d_in[11];
    const float* A_log     = (const float*)d_in[12];
    const float* Dp        = (const float*)d_in[13];
    const float* out_w     = (const float*)d_in[14];
    float* out = (float*)d_out;

    float* s = nullptr;
    cudaGetSymbolAddress((void**)&s, g_scratch);
    __half* hs = nullptr;
    cudaGetSymbolAddress((void**)&hs, g_hscratch);

    float* xz     = s + OFF_XZ;
    float* xconv  = s + OFF_XCONV;
    float* dt     = s + OFF_DT;
    float* bcm    = s + OFF_BCM;
    float* dtin_p = s + OFF_DTIN_P;
    float* bcm_p  = s + OFF_BCM_P;

    __half* xn16    = hs + HXN;
    __half* xc16    = hs + HXC;
    __half* y16     = hs + HY;
    __half* dtin16  = hs + HDTIN;
    __half* win16   = hs + HWIN;
    __half* wdtin16 = hs + HWDTIN;
    __half* wdt16   = hs + HWDT;
    __half* wbc16   = hs + HWBC;
    __half* wout16  = hs + HWOUT;

    // 0) all weight converts in one launch
    f2h_all<<<(F2H_TOTAL / 8 + 255) / 256, 256>>>(
        in_proj_w, dtin_w, dt_w, B_w, C_w, out_w, hs);

    // 1) LayerNorm -> fp16
    ln_kernel<<<MR, 256>>>(x, ln_g, ln_b, xn16);

    // 2) xz = xn @ in_proj_w^T : (2048, 4096), K=1024
    hgemm<128, EPI_NONE, false><<<dim3(4096 / 128, MR / 128), 256>>>(
        xn16, win16, xz, MR, 4096, DM_, nullptr, nullptr, 0);

    // 3) causal conv + SiLU -> fp32 + fp16
    conv_silu_kernel<<<(BB * LL * DI_ + 255) / 256, 256>>>(xz, conv_w, conv_b, xconv, xc16);

    // 4) dt_in partials: xc @ dtin_w^T : (2048, 64), K=2048, split-K=8 -> fp16 dtin
    hgemm<64, EPI_NONE, true><<<dim3(1, MR / 128, KSPLIT), 256>>>(
        xc16, wdtin16, dtin_p, MR, DTR_, DI_, nullptr, nullptr, DI_ / KSPLIT);
    reduce_kernel<true><<<(MR * DTR_ + 255) / 256, 256>>>(dtin_p, dtin16, dtin_b, MR * DTR_, DTR_);

    // 5) dt = softplus(dtin @ dt_w^T + dt_b) : (2048, 2048), K=64
    hgemm<128, EPI_SOFTPLUS, false><<<dim3(DI_ / 128, MR / 128), 256>>>(
        dtin16, wdt16, dt, MR, DI_, DTR_, dt_b, nullptr, 0);

    // 6) [B|C] partials: xc @ [B_w;C_w]^T : (2048, 32), K=2048, split-K=8
    hgemm<32, EPI_NONE, true><<<dim3(1, MR / 128, KSPLIT), 256>>>(
        xc16, wbc16, bcm_p, MR, 32, DI_, nullptr, nullptr, DI_ / KSPLIT);
    reduce_kernel<false><<<(MR * 32 + 255) / 256, 256>>>(bcm_p, bcm, nullptr, MR * 32, 32);

    // 7) selective scan + SiLU(z) gating -> fp16 y
    scan_kernel<<<(BB * DI_) / 16, 256>>>(xconv, dt, bcm, A_log, Dp, xz, y16);

    // 8) out = y @ out_w^T + residual(x) : (2048, 1024), K=2048, BN=64 for occupancy
    hgemm<64, EPI_RES, false><<<dim3(DM_ / 64, MR / 128), 256>>>(
        y16, wout16, out, MR, DM_, DI_, nullptr, x, 0);
}

// round 7
// speedup vs baseline: 3.8156x; 1.0036x over previous
#include <cuda_runtime.h>
#include <cuda_fp16.h>
#include <math.h>
#include <stdint.h>

// ---------------- problem constants ----------------
#define BB   2
#define LL   1024
#define DM_  1024
#define DI_  2048
#define NS   16
#define MR   (BB * LL)        // 2048 rows
#define DTR_ 64
#define KSPLIT 16

// ---------------- fp32 scratch ----------------
#define OFF_XZ      0                       // (MR, 2*DI)
#define OFF_XCONV   (OFF_XZ + 8388608)      // (MR, DI)
#define OFF_DT      (OFF_XCONV + 4194304)   // (MR, DI)
#define OFF_BCM     (OFF_DT + 4194304)      // (MR, 32)
#define OFF_DTIN_P  (OFF_BCM + 65536)       // (KSPLIT, MR, DTR) = 2M
#define OFF_BCM_P   (OFF_DTIN_P + 2097152)  // (KSPLIT, MR, 32)  = 1M
#define SCRATCH_FLOATS (OFF_BCM_P + 1048576)
__device__ float g_scratch[SCRATCH_FLOATS];

// ---------------- fp16 scratch ----------------
#define HXN     0                         // (MR, DM)
#define HXC     (HXN + 2097152)           // (MR, DI)
#define HY      (HXC + 4194304)           // (MR, DI)
#define HDTIN   (HY + 4194304)            // (MR, DTR)
#define HWIN    (HDTIN + 131072)          // (4096, 1024)
#define HWDTIN  (HWIN + 4194304)          // (64, 2048)
#define HWDT    (HWDTIN + 131072)         // (2048, 64)
#define HWBC    (HWDT + 131072)           // (32, 2048)
#define HWOUT   (HWBC + 65536)            // (1024, 2048)
#define SCRATCH_HALVES (HWOUT + 2097152)
__device__ __align__(256) __half g_hscratch[SCRATCH_HALVES];

// ---------------- helpers ----------------
__device__ __forceinline__ uint32_t pack_h2(float a, float b) {
    uint32_t p;
    asm("cvt.rn.f16x2.f32 %0, %1, %2;" : "=r"(p) : "f"(b), "f"(a));
    return p;
}
__device__ __forceinline__ uint32_t smem_u32(const void* p) {
    uint32_t a;
    asm("{ .reg .u64 t; cvta.to.shared.u64 t, %1; cvt.u32.u64 %0, t; }" : "=r"(a) : "l"(p));
    return a;
}
__device__ __forceinline__ void cp16(uint32_t dst, const void* src) {
    asm volatile("cp.async.cg.shared.global [%0], [%1], 16;" :: "r"(dst), "l"(src));
}
__device__ __forceinline__ void ldm_x4(uint32_t& r0, uint32_t& r1, uint32_t& r2, uint32_t& r3,
                                       uint32_t addr) {
    asm volatile("ldmatrix.sync.aligned.m8n8.x4.shared.b16 {%0,%1,%2,%3}, [%4];"
                 : "=r"(r0), "=r"(r1), "=r"(r2), "=r"(r3) : "r"(addr));
}
__device__ __forceinline__ void ldm_x2(uint32_t& r0, uint32_t& r1, uint32_t addr) {
    asm volatile("ldmatrix.sync.aligned.m8n8.x2.shared.b16 {%0,%1}, [%2];"
                 : "=r"(r0), "=r"(r1) : "r"(addr));
}

// ---------------- fused fp32 -> fp16 weight convert ----------------
#define F2H_TOTAL 6619136
__global__ void f2h_all(const float* w0, const float* w1, const float* w2,
                        const float* w3, const float* w4, const float* w5,
                        __half* hbase) {
    int i = (blockIdx.x * blockDim.x + threadIdx.x) * 8;
    if (i >= F2H_TOTAL) return;
    const float* s; __half* d; int off;
    if (i < 4194304)      { s = w0; d = hbase + HWIN;           off = i; }
    else if (i < 4325376) { s = w1; d = hbase + HWDTIN;         off = i - 4194304; }
    else if (i < 4456448) { s = w2; d = hbase + HWDT;           off = i - 4325376; }
    else if (i < 4489216) { s = w3; d = hbase + HWBC;           off = i - 4456448; }
    else if (i < 4521984) { s = w4; d = hbase + HWBC + 32768;   off = i - 4489216; }
    else                  { s = w5; d = hbase + HWOUT;          off = i - 4521984; }
    float4 a = *(const float4*)(s + off);
    float4 b = *(const float4*)(s + off + 4);
    uint4 u = { pack_h2(a.x, a.y), pack_h2(a.z, a.w), pack_h2(b.x, b.y), pack_h2(b.z, b.w) };
    *(uint4*)(d + off) = u;
}

// ---------------- LayerNorm (fp32 in -> fp16 out) ----------------
__global__ void ln_kernel(const float* __restrict__ x, const float* __restrict__ g,
                          const float* __restrict__ b, __half* __restrict__ o) {
    int row = blockIdx.x;
    int tid = threadIdx.x;
    const float4* xr = (const float4*)(x + (size_t)row * DM_);
    float4 v = xr[tid];
    float s  = v.x + v.y + v.z + v.w;
    float ss = v.x * v.x + v.y * v.y + v.z * v.z + v.w * v.w;
    #pragma unroll
    for (int off = 16; off > 0; off >>= 1) {
        s  += __shfl_xor_sync(0xffffffffu, s,  off);
        ss += __shfl_xor_sync(0xffffffffu, ss, off);
    }
    __shared__ float sh_s[8], sh_ss[8];
    int w = tid >> 5, l = tid & 31;
    if (l == 0) { sh_s[w] = s; sh_ss[w] = ss; }
    __syncthreads();
    if (w == 0) {
        s  = (l < 8) ? sh_s[l]  : 0.f;
        ss = (l < 8) ? sh_ss[l] : 0.f;
        #pragma unroll
        for (int off = 4; off > 0; off >>= 1) {
            s  += __shfl_xor_sync(0xffffffffu, s,  off);
            ss += __shfl_xor_sync(0xffffffffu, ss, off);
        }
        if (l == 0) { sh_s[0] = s; sh_ss[0] = ss; }
    }
    __syncthreads();
    float mu  = sh_s[0] * (1.0f / DM_);
    float var = sh_ss[0] * (1.0f / DM_) - mu * mu;
    float inv = rsqrtf(var + 1e-5f);
    float4 gg = ((const float4*)g)[tid];
    float4 bb = ((const float4*)b)[tid];
    float r0 = (v.x - mu) * inv * gg.x + bb.x;
    float r1 = (v.y - mu) * inv * gg.y + bb.y;
    float r2 = (v.z - mu) * inv * gg.z + bb.z;
    float r3 = (v.w - mu) * inv * gg.w + bb.w;
    uint2 u = { pack_h2(r0, r1), pack_h2(r2, r3) };
    *(uint2*)(o + (size_t)row * DM_ + tid * 4) = u;
}

// ---------------- fp16 HMMA GEMM, BK=64 (128B rows), cp.async 3-stage ----------------
// A (M,K) fp16 rm, B (N,K) fp16 rm, C (M,N) fp32 = A*B^T.
// smem row = 128B = 8 x 16B chunks; swizzle chunk' = ch ^ (r & 7).
enum { EPI_NONE = 0, EPI_SOFTPLUS = 2, EPI_RES = 3 };

extern __shared__ uint8_t dynsm[];

template<int BN, int EPI, bool SPLITK>
__global__ void __launch_bounds__(256)
hgemm(const __half* __restrict__ A, const __half* __restrict__ Bw,
      float* __restrict__ C, int M, int N, int K,
      const float* __restrict__ bias, const float* __restrict__ res,
      int ksplit_len) {
    constexpr int BK = 64;                 // halves per row
    constexpr int ROWS = 128 + BN;
    constexpr int STAGE_B = ROWS * 128;    // bytes per stage
    constexpr int WN = BN / 4;
    constexpr int MI = 4;
    constexpr int NI = WN / 8;             // 4 / 2 / 1
    constexpr int ACH = 128 * 8;           // A 16B chunks per tile
    constexpr int BCH = BN * 8;

    const int tid  = threadIdx.x;
    const int warp = tid >> 5, lane = tid & 31;
    const int g  = lane >> 2, tg = lane & 3;
    const int wm = (warp & 1) * 64;
    const int wn = (warp >> 1) * WN;
    const int bm = blockIdx.y * 128;
    const int bn = blockIdx.x * BN;
    const uint32_t smb = smem_u32(dynsm);

    const int lrow   = lane & 7;
    const int a_radd = ((lane >> 3) & 1) * 8;
    const int a_chad = (lane >> 4) & 1;
    const int b_radd = ((lane >> 4) & 1) * 8;
    const int b_chad = (lane >> 3) & 1;

    int k_begin = 0, k_len = K;
    if (SPLITK) { k_begin = blockIdx.z * ksplit_len; k_len = ksplit_len; }
    const int NT = k_len / BK;

    const __half* Ag = A + (size_t)bm * K + k_begin;
    const __half* Bg = Bw + (size_t)bn * K + k_begin;

    auto load_tile = [&](int st, int kt) {
        const uint32_t sb = smb + st * STAGE_B;
        const int k0 = kt * BK;
        #pragma unroll
        for (int i = 0; i < ACH / 256; i++) {
            int idx = tid + i * 256;
            int r = idx >> 3, ch = idx & 7;
            uint32_t dst = sb + r * 128 + ((ch ^ (r & 7)) << 4);
            cp16(dst, Ag + (size_t)r * K + k0 + ch * 8);
        }
        #pragma unroll
        for (int i = 0; i < (BCH + 255) / 256; i++) {
            int idx = tid + i * 256;
            if (BCH % 256 == 0 || idx < BCH) {
                int r = idx >> 3, ch = idx & 7;
                uint32_t dst = sb + (128 + r) * 128 + ((ch ^ (r & 7)) << 4);
                cp16(dst, Bg + (size_t)r * K + k0 + ch * 8);
            }
        }
    };

    float c[MI][NI][4];
    #pragma unroll
    for (int mi = 0; mi < MI; mi++)
        #pragma unroll
        for (int ni = 0; ni < NI; ni++)
            #pragma unroll
            for (int q = 0; q < 4; q++) c[mi][ni][q] = 0.f;

    if (0 < NT) load_tile(0, 0);
    asm volatile("cp.async.commit_group;" ::: "memory");
    if (1 < NT) load_tile(1, 1);
    asm volatile("cp.async.commit_group;" ::: "memory");

    for (int it = 0; it < NT; it++) {
        const int st = it % 3;
        asm volatile("cp.async.wait_group 1;" ::: "memory");
        __syncthreads();
        if (it + 2 < NT) load_tile((it + 2) % 3, it + 2);
        asm volatile("cp.async.commit_group;" ::: "memory");

        const uint32_t smt = smb + st * STAGE_B;
        #pragma unroll
        for (int kk = 0; kk < 4; kk++) {
            uint32_t af[MI][4], bf[NI][2];
            #pragma unroll
            for (int mi = 0; mi < MI; mi++) {
                int r  = wm + mi * 16 + lrow + a_radd;
                int ch = 2 * kk + a_chad;
                uint32_t addr = smt + r * 128 + ((ch ^ (r & 7)) << 4);
                ldm_x4(af[mi][0], af[mi][1], af[mi][2], af[mi][3], addr);
            }
            if (NI == 1) {
                int rr = 128 + wn + lrow;
                int ch = 2 * kk + ((lane >> 3) & 1);
                uint32_t addr = smt + rr * 128 + ((ch ^ (rr & 7)) << 4);
                ldm_x2(bf[0][0], bf[0][1], addr);
            } else {
                #pragma unroll
                for (int ng = 0; ng < NI / 2; ng++) {
                    int r  = 128 + wn + ng * 16 + lrow + b_radd;
                    int ch = 2 * kk + b_chad;
                    uint32_t addr = smt + r * 128 + ((ch ^ (r & 7)) << 4);
                    uint32_t r0, r1, r2, r3;
                    ldm_x4(r0, r1, r2, r3, addr);
                    bf[2 * ng][0] = r0; bf[2 * ng][1] = r1;
                    bf[2 * ng + 1][0] = r2; bf[2 * ng + 1][1] = r3;
                }
            }
            #pragma unroll
            for (int mi = 0; mi < MI; mi++)
                #pragma unroll
                for (int ni = 0; ni < NI; ni++) {
                    asm volatile(
                        "mma.sync.aligned.m16n8k16.row.col.f32.f16.f16.f32 "
                        "{%0,%1,%2,%3}, {%4,%5,%6,%7}, {%8,%9}, {%0,%1,%2,%3};"
                        : "+f"(c[mi][ni][0]), "+f"(c[mi][ni][1]),
                          "+f"(c[mi][ni][2]), "+f"(c[mi][ni][3])
                        : "r"(af[mi][0]), "r"(af[mi][1]), "r"(af[mi][2]), "r"(af[mi][3]),
                          "r"(bf[ni][0]), "r"(bf[ni][1]));
                }
        }
        __syncthreads();
    }

    float* Cb = C;
    if (SPLITK) Cb += (size_t)blockIdx.z * (size_t)M * N;
    #pragma unroll
    for (int mi = 0; mi < MI; mi++) {
        #pragma unroll
        for (int ni = 0; ni < NI; ni++) {
            int coln = bn + wn + ni * 8 + tg * 2;
            #pragma unroll
            for (int h = 0; h < 2; h++) {
                int row = bm + wm + mi * 16 + g + h * 8;
                float v0 = c[mi][ni][2 * h + 0];
                float v1 = c[mi][ni][2 * h + 1];
                if (EPI == EPI_SOFTPLUS) {
                    v0 += bias[coln]; v1 += bias[coln + 1];
                    v0 = (v0 > 20.f) ? v0 : log1pf(expf(v0));
                    v1 = (v1 > 20.f) ? v1 : log1pf(expf(v1));
                } else if (EPI == EPI_RES) {
                    float2 rr = *(const float2*)&res[(size_t)row * N + coln];
                    v0 += rr.x; v1 += rr.y;
                }
                float2 out = { v0, v1 };
                *(float2*)&Cb[(size_t)row * N + coln] = out;
            }
        }
    }
}

// ---------------- split-K reduce ----------------
template<bool HALF_OUT>
__global__ void reduce_kernel(const float* __restrict__ part, void* __restrict__ out,
                              const float* __restrict__ bias, int MN, int Ncols) {
    int i = blockIdx.x * blockDim.x + threadIdx.x;
    if (i >= MN) return;
    float s = bias ? bias[i % Ncols] : 0.f;
    #pragma unroll
    for (int p = 0; p < KSPLIT; p++) s += part[(size_t)p * MN + i];
    if (HALF_OUT) ((__half*)out)[i] = __float2half(s);
    else          ((float*)out)[i] = s;
}

// ---------------- causal depthwise conv (k=4) + SiLU, 4 channels/thread ----------------
__global__ void conv_silu_kernel(const float* __restrict__ xz,
                                 const float* __restrict__ w,
                                 const float* __restrict__ cb,
                                 float* __restrict__ xc32,
                                 __half* __restrict__ xc16) {
    int idx = blockIdx.x * blockDim.x + threadIdx.x;     // over BB*LL*(DI/4)
    if (idx >= BB * LL * (DI_ / 4)) return;
    int d4 = (idx % (DI_ / 4)) * 4;
    int t  = (idx / (DI_ / 4)) % LL;
    int b  = idx / ((DI_ / 4) * LL);

    float wr[4][4];
    #pragma unroll
    for (int j = 0; j < 4; j++) {
        float4 wj = *(const float4*)(w + (d4 + j) * 4);
        wr[j][0] = wj.x; wr[j][1] = wj.y; wr[j][2] = wj.z; wr[j][3] = wj.w;
    }
    float4 bias = *(const float4*)(cb + d4);
    float ac[4] = { bias.x, bias.y, bias.z, bias.w };

    const float* base = xz + (size_t)b * LL * (2 * DI_) + d4;
    #pragma unroll
    for (int k = 0; k < 4; k++) {
        int ts = t - 3 + k;
        if (ts >= 0) {
            float4 xv = *(const float4*)(base + (size_t)ts * (2 * DI_));
            ac[0] = fmaf(wr[0][k], xv.x, ac[0]);
            ac[1] = fmaf(wr[1][k], xv.y, ac[1]);
            ac[2] = fmaf(wr[2][k], xv.z, ac[2]);
            ac[3] = fmaf(wr[3][k], xv.w, ac[3]);
        }
    }
    float v[4];
    #pragma unroll
    for (int j = 0; j < 4; j++) v[j] = ac[j] / (1.f + __expf(-ac[j]));

    size_t o = (size_t)b * LL * DI_ + (size_t)t * DI_ + d4;
    float4 ov = { v[0], v[1], v[2], v[3] };
    *(float4*)(xc32 + o) = ov;
    uint2 hv = { pack_h2(v[0], v[1]), pack_h2(v[2], v[3]) };
    *(uint2*)(xc16 + o) = hv;
}

// ---------------- selective scan + SiLU(z) gating ----------------
__global__ void scan_kernel(const float* __restrict__ xconv,
                            const float* __restrict__ dt,
                            const float* __restrict__ bcm,
                            const float* __restrict__ A_log,
                            const float* __restrict__ Dp,
                            const float* __restrict__ xz,
                            __half* __restrict__ y) {
    int half = threadIdx.x >> 4;
    int lane = threadIdx.x & 15;
    int ch = blockIdx.x * (blockDim.x >> 4) + half;
    int b = ch / DI_;
    int d = ch % DI_;

    float a  = -expf(A_log[d * NS + lane]);
    float Dd = Dp[d];
    float h  = 0.f;

    const float* dtp = dt    + (size_t)b * LL * DI_ + d;
    const float* up  = xconv + (size_t)b * LL * DI_ + d;
    const float* bcp = bcm   + (size_t)b * LL * 32;
    const float* zp  = xz    + (size_t)b * LL * (2 * DI_) + DI_ + d;
    __half*      yp  = y     + (size_t)b * LL * DI_ + d;

    float dtb[4], ub[4], Bb[4], Cb[4], zb[4];
    #pragma unroll
    for (int j = 0; j < 4; j++) {
        dtb[j] = dtp[(size_t)j * DI_];
        ub[j]  = up[(size_t)j * DI_];
        Bb[j]  = bcp[j * 32 + lane];
        Cb[j]  = bcp[j * 32 + 16 + lane];
        zb[j]  = (lane == 0) ? zp[(size_t)j * (2 * DI_)] : 0.f;
    }

    #pragma unroll 4
    for (int t = 0; t < LL; t++) {
        int j = t & 3;
        float dtv = dtb[j], uv = ub[j], Bn = Bb[j], Cn = Cb[j], zv = zb[j];
        int tn = t + 4;
        if (tn < LL) {
            dtb[j] = dtp[(size_t)tn * DI_];
            ub[j]  = up[(size_t)tn * DI_];
            Bb[j]  = bcp[tn * 32 + lane];
            Cb[j]  = bcp[tn * 32 + 16 + lane];
            zb[j]  = (lane == 0) ? zp[(size_t)tn * (2 * DI_)] : 0.f;
        }
        float dA = __expf(dtv * a);
        h = fmaf(h, dA, dtv * uv * Bn);
        float p = h * Cn;
        p += __shfl_xor_sync(0xffffffffu, p, 8);
        p += __shfl_xor_sync(0xffffffffu, p, 4);
        p += __shfl_xor_sync(0xffffffffu, p, 2);
        p += __shfl_xor_sync(0xffffffffu, p, 1);
        if (lane == 0) {
            float sz = zv / (1.f + __expf(-zv));
            yp[(size_t)t * DI_] = __float2half((p + uv * Dd) * sz);
        }
    }
}

// ---------------- launch ----------------
extern "C" void kernel_launch(void* const* d_in, const int* in_sizes, int n_in,
                              void* d_out, int out_size) {
    const float* x         = (const float*)d_in[0];
    const float* ln_g      = (const float*)d_in[1];
    const float* ln_b      = (const float*)d_in[2];
    const float* in_proj_w = (const float*)d_in[3];
    const float* conv_w    = (const float*)d_in[4];
    const float* conv_b    = (const float*)d_in[5];
    const float* dtin_w    = (const float*)d_in[6];
    const float* dtin_b    = (const float*)d_in[7];
    const float* dt_w      = (const float*)d_in[8];
    const float* dt_b      = (const float*)d_in[9];
    const float* B_w       = (const float*)d_in[10];
    const float* C_w       = (const float*)d_in[11];
    const float* A_log     = (const float*)d_in[12];
    const float* Dp        = (const float*)d_in[13];
    const float* out_w     = (const float*)d_in[14];
    float* out = (float*)d_out;

    float* s = nullptr;
    cudaGetSymbolAddress((void**)&s, g_scratch);
    __half* hs = nullptr;
    cudaGetSymbolAddress((void**)&hs, g_hscratch);

    float* xz     = s + OFF_XZ;
    float* xconv  = s + OFF_XCONV;
    float* dt     = s + OFF_DT;
    float* bcm    = s + OFF_BCM;
    float* dtin_p = s + OFF_DTIN_P;
    float* bcm_p  = s + OFF_BCM_P;

    __half* xn16    = hs + HXN;
    __half* xc16    = hs + HXC;
    __half* y16     = hs + HY;
    __half* dtin16  = hs + HDTIN;
    __half* win16   = hs + HWIN;
    __half* wdtin16 = hs + HWDTIN;
    __half* wdt16   = hs + HWDT;
    __half* wbc16   = hs + HWBC;
    __half* wout16  = hs + HWOUT;

    const int SM128 = 3 * (128 + 128) * 128;   // 98304
    const int SM64  = 3 * (128 + 64) * 128;    // 73728
    const int SM32  = 3 * (128 + 32) * 128;    // 61440
    cudaFuncSetAttribute(hgemm<128, EPI_NONE,     false>, cudaFuncAttributeMaxDynamicSharedMemorySize, SM128);
    cudaFuncSetAttribute(hgemm<64,  EPI_NONE,     true >, cudaFuncAttributeMaxDynamicSharedMemorySize, SM64);
    cudaFuncSetAttribute(hgemm<128, EPI_SOFTPLUS, false>, cudaFuncAttributeMaxDynamicSharedMemorySize, SM128);
    cudaFuncSetAttribute(hgemm<32,  EPI_NONE,     true >, cudaFuncAttributeMaxDynamicSharedMemorySize, SM32);
    cudaFuncSetAttribute(hgemm<64,  EPI_RES,      false>, cudaFuncAttributeMaxDynamicSharedMemorySize, SM64);

    // 0) weight converts (single launch)
    f2h_all<<<(F2H_TOTAL / 8 + 255) / 256, 256>>>(
        in_proj_w, dtin_w, dt_w, B_w, C_w, out_w, hs);

    // 1) LayerNorm -> fp16
    ln_kernel<<<MR, 256>>>(x, ln_g, ln_b, xn16);

    // 2) xz = xn @ in_proj_w^T : (2048, 4096), K=1024
    hgemm<128, EPI_NONE, false><<<dim3(4096 / 128, MR / 128), 256, SM128>>>(
        xn16, win16, xz, MR, 4096, DM_, nullptr, nullptr, 0);

    // 3) causal conv + SiLU -> fp32 + fp16
    conv_silu_kernel<<<(BB * LL * (DI_ / 4) + 255) / 256, 256>>>(xz, conv_w, conv_b, xconv, xc16);

    // 4) dt_in partials: (2048, 64), K=2048, split-K=16
    hgemm<64, EPI_NONE, true><<<dim3(1, MR / 128, KSPLIT), 256, SM64>>>(
        xc16, wdtin16, dtin_p, MR, DTR_, DI_, nullptr, nullptr, DI_ / KSPLIT);
    reduce_kernel<true><<<(MR * DTR_ + 255) / 256, 256>>>(dtin_p, dtin16, dtin_b, MR * DTR_, DTR_);

    // 5) dt = softplus(dtin @ dt_w^T + dt_b) : (2048, 2048), K=64
    hgemm<128, EPI_SOFTPLUS, false><<<dim3(DI_ / 128, MR / 128), 256, SM128>>>(
        dtin16, wdt16, dt, MR, DI_, DTR_, dt_b, nullptr, 0);

    // 6) [B|C] partials: (2048, 32), K=2048, split-K=16
    hgemm<32, EPI_NONE, true><<<dim3(1, MR / 128, KSPLIT), 256, SM32>>>(
        xc16, wbc16, bcm_p, MR, 32, DI_, nullptr, nullptr, DI_ / KSPLIT);
    reduce_kernel<false><<<(MR * 32 + 255) / 256, 256>>>(bcm_p, bcm, nullptr, MR * 32, 32);

    // 7) selective scan + SiLU(z) gating -> fp16 y
    scan_kernel<<<(BB * DI_) / 16, 256>>>(xconv, dt, bcm, A_log, Dp, xz, y16);

    // 8) out = y @ out_w^T + residual(x) : (2048, 1024), K=2048
    hgemm<64, EPI_RES, false><<<dim3(DM_ / 64, MR / 128), 256, SM64>>>(
        y16, wout16, out, MR, DM_, DI_, nullptr, x, 0);
}

// round 8
// speedup vs baseline: 3.8217x; 1.0016x over previous
#include <cuda_runtime.h>
#include <cuda_fp16.h>
#include <math.h>
#include <stdint.h>

// ---------------- problem constants ----------------
#define BB   2
#define LL   1024
#define DM_  1024
#define DI_  2048
#define NS   16
#define MR   (BB * LL)        // 2048 rows
#define DTR_ 64
#define KSPLIT 16

// ---------------- fp32 scratch ----------------
#define OFF_XZ      0                       // (MR, 2*DI)
#define OFF_XCONV   (OFF_XZ + 8388608)      // (MR, DI)
#define OFF_DT      (OFF_XCONV + 4194304)   // (MR, DI)
#define OFF_BCM     (OFF_DT + 4194304)      // (MR, 32)
#define OFF_MERG_P  (OFF_BCM + 65536)       // (KSPLIT, MR, 96) = 3145728
#define SCRATCH_FLOATS (OFF_MERG_P + 3145728)
__device__ float g_scratch[SCRATCH_FLOATS];

// ---------------- fp16 scratch ----------------
#define HXN     0                         // (MR, DM)
#define HXC     (HXN + 2097152)           // (MR, DI)
#define HY      (HXC + 4194304)           // (MR, DI)
#define HDTIN   (HY + 4194304)            // (MR, DTR)
#define HWIN    (HDTIN + 131072)          // (4096, 1024)
#define HWMERG  (HWIN + 4194304)          // (96, 2048) = dtin_w | B_w | C_w
#define HWDT    (HWMERG + 196608)         // (2048, 64)
#define HWOUT   (HWDT + 131072)           // (1024, 2048)
#define SCRATCH_HALVES (HWOUT + 2097152)
__device__ __align__(256) __half g_hscratch[SCRATCH_HALVES];

// ---------------- helpers ----------------
__device__ __forceinline__ uint32_t pack_h2(float a, float b) {
    uint32_t p;
    asm("cvt.rn.f16x2.f32 %0, %1, %2;" : "=r"(p) : "f"(b), "f"(a));
    return p;
}
__device__ __forceinline__ uint32_t smem_u32(const void* p) {
    uint32_t a;
    asm("{ .reg .u64 t; cvta.to.shared.u64 t, %1; cvt.u32.u64 %0, t; }" : "=r"(a) : "l"(p));
    return a;
}
__device__ __forceinline__ void cp16(uint32_t dst, const void* src) {
    asm volatile("cp.async.cg.shared.global [%0], [%1], 16;" :: "r"(dst), "l"(src));
}
__device__ __forceinline__ void ldm_x4(uint32_t& r0, uint32_t& r1, uint32_t& r2, uint32_t& r3,
                                       uint32_t addr) {
    asm volatile("ldmatrix.sync.aligned.m8n8.x4.shared.b16 {%0,%1,%2,%3}, [%4];"
                 : "=r"(r0), "=r"(r1), "=r"(r2), "=r"(r3) : "r"(addr));
}
__device__ __forceinline__ void ldm_x2(uint32_t& r0, uint32_t& r1, uint32_t addr) {
    asm volatile("ldmatrix.sync.aligned.m8n8.x2.shared.b16 {%0,%1}, [%2];"
                 : "=r"(r0), "=r"(r1) : "r"(addr));
}

// ---------------- fused fp32 -> fp16 weight convert ----------------
// win 4194304 | merged[dtin 131072 | B 32768 | C 32768] | wdt 131072 | wout 2097152
#define F2H_TOTAL 6619136
__global__ void f2h_all(const float* w0, const float* w1, const float* w2,
                        const float* w3, const float* w4, const float* w5,
                        __half* hbase) {
    int i = (blockIdx.x * blockDim.x + threadIdx.x) * 8;
    if (i >= F2H_TOTAL) return;
    const float* s; __half* d; int off;
    if (i < 4194304)      { s = w0; d = hbase + HWIN;            off = i; }
    else if (i < 4325376) { s = w1; d = hbase + HWMERG;          off = i - 4194304; }   // dtin_w
    else if (i < 4358144) { s = w3; d = hbase + HWMERG + 131072; off = i - 4325376; }   // B_w
    else if (i < 4390912) { s = w4; d = hbase + HWMERG + 163840; off = i - 4358144; }   // C_w
    else if (i < 4521984) { s = w2; d = hbase + HWDT;            off = i - 4390912; }   // dt_w
    else                  { s = w5; d = hbase + HWOUT;           off = i - 4521984; }   // out_w
    float4 a = *(const float4*)(s + off);
    float4 b = *(const float4*)(s + off + 4);
    uint4 u = { pack_h2(a.x, a.y), pack_h2(a.z, a.w), pack_h2(b.x, b.y), pack_h2(b.z, b.w) };
    *(uint4*)(d + off) = u;
}

// ---------------- LayerNorm (fp32 in -> fp16 out) ----------------
__global__ void ln_kernel(const float* __restrict__ x, const float* __restrict__ g,
                          const float* __restrict__ b, __half* __restrict__ o) {
    int row = blockIdx.x;
    int tid = threadIdx.x;
    const float4* xr = (const float4*)(x + (size_t)row * DM_);
    float4 v = xr[tid];
    float s  = v.x + v.y + v.z + v.w;
    float ss = v.x * v.x + v.y * v.y + v.z * v.z + v.w * v.w;
    #pragma unroll
    for (int off = 16; off > 0; off >>= 1) {
        s  += __shfl_xor_sync(0xffffffffu, s,  off);
        ss += __shfl_xor_sync(0xffffffffu, ss, off);
    }
    __shared__ float sh_s[8], sh_ss[8];
    int w = tid >> 5, l = tid & 31;
    if (l == 0) { sh_s[w] = s; sh_ss[w] = ss; }
    __syncthreads();
    if (w == 0) {
        s  = (l < 8) ? sh_s[l]  : 0.f;
        ss = (l < 8) ? sh_ss[l] : 0.f;
        #pragma unroll
        for (int off = 4; off > 0; off >>= 1) {
            s  += __shfl_xor_sync(0xffffffffu, s,  off);
            ss += __shfl_xor_sync(0xffffffffu, ss, off);
        }
        if (l == 0) { sh_s[0] = s; sh_ss[0] = ss; }
    }
    __syncthreads();
    float mu  = sh_s[0] * (1.0f / DM_);
    float var = sh_ss[0] * (1.0f / DM_) - mu * mu;
    float inv = rsqrtf(var + 1e-5f);
    float4 gg = ((const float4*)g)[tid];
    float4 bb = ((const float4*)b)[tid];
    float r0 = (v.x - mu) * inv * gg.x + bb.x;
    float r1 = (v.y - mu) * inv * gg.y + bb.y;
    float r2 = (v.z - mu) * inv * gg.z + bb.z;
    float r3 = (v.w - mu) * inv * gg.w + bb.w;
    uint2 u = { pack_h2(r0, r1), pack_h2(r2, r3) };
    *(uint2*)(o + (size_t)row * DM_ + tid * 4) = u;
}

// ---------------- fp16 HMMA GEMM, BK=64, cp.async 3-stage, 2 CTA/SM ----------------
enum { EPI_NONE = 0, EPI_SOFTPLUS = 2, EPI_RES = 3 };

extern __shared__ uint8_t dynsm[];

template<int BN, int EPI, bool SPLITK>
__global__ void __launch_bounds__(256, 2)
hgemm(const __half* __restrict__ A, const __half* __restrict__ Bw,
      float* __restrict__ C, int M, int N, int K,
      const float* __restrict__ bias, const float* __restrict__ res,
      int ksplit_len) {
    constexpr int BK = 64;
    constexpr int ROWS = 128 + BN;
    constexpr int STAGE_B = ROWS * 128;
    constexpr int WN = BN / 4;
    constexpr int MI = 4;
    constexpr int NI = WN / 8;             // 2 (BN=64) / 3 (BN=96)
    constexpr int ACH = 128 * 8;
    constexpr int BCH = BN * 8;

    const int tid  = threadIdx.x;
    const int warp = tid >> 5, lane = tid & 31;
    const int g  = lane >> 2, tg = lane & 3;
    const int wm = (warp & 1) * 64;
    const int wn = (warp >> 1) * WN;
    const int bm = blockIdx.y * 128;
    const int bn = blockIdx.x * BN;
    const uint32_t smb = smem_u32(dynsm);

    const int lrow   = lane & 7;
    const int a_radd = ((lane >> 3) & 1) * 8;
    const int a_chad = (lane >> 4) & 1;
    const int b_radd = ((lane >> 4) & 1) * 8;
    const int b_chad = (lane >> 3) & 1;

    int k_begin = 0, k_len = K;
    if (SPLITK) { k_begin = blockIdx.z * ksplit_len; k_len = ksplit_len; }
    const int NT = k_len / BK;

    const __half* Ag = A + (size_t)bm * K + k_begin;
    const __half* Bg = Bw + (size_t)bn * K + k_begin;

    auto load_tile = [&](int st, int kt) {
        const uint32_t sb = smb + st * STAGE_B;
        const int k0 = kt * BK;
        #pragma unroll
        for (int i = 0; i < ACH / 256; i++) {
            int idx = tid + i * 256;
            int r = idx >> 3, ch = idx & 7;
            uint32_t dst = sb + r * 128 + ((ch ^ (r & 7)) << 4);
            cp16(dst, Ag + (size_t)r * K + k0 + ch * 8);
        }
        #pragma unroll
        for (int i = 0; i < (BCH + 255) / 256; i++) {
            int idx = tid + i * 256;
            if (BCH % 256 == 0 || idx < BCH) {
                int r = idx >> 3, ch = idx & 7;
                uint32_t dst = sb + (128 + r) * 128 + ((ch ^ (r & 7)) << 4);
                cp16(dst, Bg + (size_t)r * K + k0 + ch * 8);
            }
        }
    };

    float c[MI][NI][4];
    #pragma unroll
    for (int mi = 0; mi < MI; mi++)
        #pragma unroll
        for (int ni = 0; ni < NI; ni++)
            #pragma unroll
            for (int q = 0; q < 4; q++) c[mi][ni][q] = 0.f;

    if (0 < NT) load_tile(0, 0);
    asm volatile("cp.async.commit_group;" ::: "memory");
    if (1 < NT) load_tile(1, 1);
    asm volatile("cp.async.commit_group;" ::: "memory");

    for (int it = 0; it < NT; it++) {
        const int st = it % 3;
        asm volatile("cp.async.wait_group 1;" ::: "memory");
        __syncthreads();
        if (it + 2 < NT) load_tile((it + 2) % 3, it + 2);
        asm volatile("cp.async.commit_group;" ::: "memory");

        const uint32_t smt = smb + st * STAGE_B;
        #pragma unroll
        for (int kk = 0; kk < 4; kk++) {
            uint32_t af[MI][4], bf[NI][2];
            #pragma unroll
            for (int mi = 0; mi < MI; mi++) {
                int r  = wm + mi * 16 + lrow + a_radd;
                int ch = 2 * kk + a_chad;
                uint32_t addr = smt + r * 128 + ((ch ^ (r & 7)) << 4);
                ldm_x4(af[mi][0], af[mi][1], af[mi][2], af[mi][3], addr);
            }
            #pragma unroll
            for (int ng = 0; ng < NI / 2; ng++) {
                int r  = 128 + wn + ng * 16 + lrow + b_radd;
                int ch = 2 * kk + b_chad;
                uint32_t addr = smt + r * 128 + ((ch ^ (r & 7)) << 4);
                uint32_t r0, r1, r2, r3;
                ldm_x4(r0, r1, r2, r3, addr);
                bf[2 * ng][0] = r0; bf[2 * ng][1] = r1;
                bf[2 * ng + 1][0] = r2; bf[2 * ng + 1][1] = r3;
            }
            if (NI & 1) {                       // odd tail (BN=96)
                int rr = 128 + wn + (NI - 1) * 8 + lrow;
                int ch = 2 * kk + ((lane >> 3) & 1);
                uint32_t addr = smt + rr * 128 + ((ch ^ (rr & 7)) << 4);
                ldm_x2(bf[NI - 1][0], bf[NI - 1][1], addr);
            }
            #pragma unroll
            for (int mi = 0; mi < MI; mi++)
                #pragma unroll
                for (int ni = 0; ni < NI; ni++) {
                    asm volatile(
                        "mma.sync.aligned.m16n8k16.row.col.f32.f16.f16.f32 "
                        "{%0,%1,%2,%3}, {%4,%5,%6,%7}, {%8,%9}, {%0,%1,%2,%3};"
                        : "+f"(c[mi][ni][0]), "+f"(c[mi][ni][1]),
                          "+f"(c[mi][ni][2]), "+f"(c[mi][ni][3])
                        : "r"(af[mi][0]), "r"(af[mi][1]), "r"(af[mi][2]), "r"(af[mi][3]),
                          "r"(bf[ni][0]), "r"(bf[ni][1]));
                }
        }
        __syncthreads();
    }

    float* Cb = C;
    if (SPLITK) Cb += (size_t)blockIdx.z * (size_t)M * N;
    #pragma unroll
    for (int mi = 0; mi < MI; mi++) {
        #pragma unroll
        for (int ni = 0; ni < NI; ni++) {
            int coln = bn + wn + ni * 8 + tg * 2;
            #pragma unroll
            for (int h = 0; h < 2; h++) {
                int row = bm + wm + mi * 16 + g + h * 8;
                float v0 = c[mi][ni][2 * h + 0];
                float v1 = c[mi][ni][2 * h + 1];
                if (EPI == EPI_SOFTPLUS) {
                    v0 += bias[coln]; v1 += bias[coln + 1];
                    v0 = (v0 > 20.f) ? v0 : log1pf(expf(v0));
                    v1 = (v1 > 20.f) ? v1 : log1pf(expf(v1));
                } else if (EPI == EPI_RES) {
                    float2 rr = *(const float2*)&res[(size_t)row * N + coln];
                    v0 += rr.x; v1 += rr.y;
                }
                float2 out = { v0, v1 };
                *(float2*)&Cb[(size_t)row * N + coln] = out;
            }
        }
    }
}

// ---------------- merged split-K reduce: cols 0-63 -> dtin16(+bias), 64-95 -> bcm ----------------
__global__ void reduce_merged(const float* __restrict__ part, __half* __restrict__ dtin16,
                              float* __restrict__ bcm, const float* __restrict__ dtin_b) {
    int i = blockIdx.x * blockDim.x + threadIdx.x;
    if (i >= MR * 96) return;
    int row = i / 96, col = i % 96;
    float s = 0.f;
    #pragma unroll
    for (int p = 0; p < KSPLIT; p++) s += part[(size_t)p * (MR * 96) + i];
    if (col < 64) dtin16[row * 64 + col] = __float2half(s + dtin_b[col]);
    else          bcm[row * 32 + (col - 64)] = s;
}

// ---------------- causal depthwise conv (k=4) + SiLU (scalar, dual out) ----------------
__global__ void conv_silu_kernel(const float* __restrict__ xz,
                                 const float* __restrict__ w,
                                 const float* __restrict__ cb,
                                 float* __restrict__ xc32,
                                 __half* __restrict__ xc16) {
    int idx = blockIdx.x * blockDim.x + threadIdx.x;
    if (idx >= BB * LL * DI_) return;
    int d = idx % DI_;
    int t = (idx / DI_) % LL;
    int b = idx / (DI_ * LL);
    const float* base = xz + (size_t)b * LL * (2 * DI_) + d;
    float acc = cb[d];
    #pragma unroll
    for (int k = 0; k < 4; k++) {
        int ts = t - 3 + k;
        if (ts >= 0) acc = fmaf(w[d * 4 + k], base[(size_t)ts * (2 * DI_)], acc);
    }
    float sg = 1.f / (1.f + __expf(-acc));
    float v = acc * sg;
    xc32[idx] = v;
    xc16[idx] = __float2half(v);
}

// ---------------- selective scan + SiLU(z) gating ----------------
__global__ void scan_kernel(const float* __restrict__ xconv,
                            const float* __restrict__ dt,
                            const float* __restrict__ bcm,
                            const float* __restrict__ A_log,
                            const float* __restrict__ Dp,
                            const float* __restrict__ xz,
                            __half* __restrict__ y) {
    int half = threadIdx.x >> 4;
    int lane = threadIdx.x & 15;
    int ch = blockIdx.x * (blockDim.x >> 4) + half;
    int b = ch / DI_;
    int d = ch % DI_;

    float a  = -expf(A_log[d * NS + lane]);
    float Dd = Dp[d];
    float h  = 0.f;

    const float* dtp = dt    + (size_t)b * LL * DI_ + d;
    const float* up  = xconv + (size_t)b * LL * DI_ + d;
    const float* bcp = bcm   + (size_t)b * LL * 32;
    const float* zp  = xz    + (size_t)b * LL * (2 * DI_) + DI_ + d;
    __half*      yp  = y     + (size_t)b * LL * DI_ + d;

    float dtb[4], ub[4], Bb[4], Cb[4], zb[4];
    #pragma unroll
    for (int j = 0; j < 4; j++) {
        dtb[j] = dtp[(size_t)j * DI_];
        ub[j]  = up[(size_t)j * DI_];
        Bb[j]  = bcp[j * 32 + lane];
        Cb[j]  = bcp[j * 32 + 16 + lane];
        zb[j]  = (lane == 0) ? zp[(size_t)j * (2 * DI_)] : 0.f;
    }

    #pragma unroll 4
    for (int t = 0; t < LL; t++) {
        int j = t & 3;
        float dtv = dtb[j], uv = ub[j], Bn = Bb[j], Cn = Cb[j], zv = zb[j];
        int tn = t + 4;
        if (tn < LL) {
            dtb[j] = dtp[(size_t)tn * DI_];
            ub[j]  = up[(size_t)tn * DI_];
            Bb[j]  = bcp[tn * 32 + lane];
            Cb[j]  = bcp[tn * 32 + 16 + lane];
            zb[j]  = (lane == 0) ? zp[(size_t)tn * (2 * DI_)] : 0.f;
        }
        float dA = __expf(dtv * a);
        h = fmaf(h, dA, dtv * uv * Bn);
        float p = h * Cn;
        p += __shfl_xor_sync(0xffffffffu, p, 8);
        p += __shfl_xor_sync(0xffffffffu, p, 4);
        p += __shfl_xor_sync(0xffffffffu, p, 2);
        p += __shfl_xor_sync(0xffffffffu, p, 1);
        if (lane == 0) {
            float sz = zv / (1.f + __expf(-zv));
            yp[(size_t)t * DI_] = __float2half((p + uv * Dd) * sz);
        }
    }
}

// ---------------- launch ----------------
extern "C" void kernel_launch(void* const* d_in, const int* in_sizes, int n_in,
                              void* d_out, int out_size) {
    const float* x         = (const float*)d_in[0];
    const float* ln_g      = (const float*)d_in[1];
    const float* ln_b      = (const float*)d_in[2];
    const float* in_proj_w = (const float*)d_in[3];
    const float* conv_w    = (const float*)d_in[4];
    const float* conv_b    = (const float*)d_in[5];
    const float* dtin_w    = (const float*)d_in[6];
    const float* dtin_b    = (const float*)d_in[7];
    const float* dt_w      = (const float*)d_in[8];
    const float* dt_b      = (const float*)d_in[9];
    const float* B_w       = (const float*)d_in[10];
    const float* C_w       = (const float*)d_in[11];
    const float* A_log     = (const float*)d_in[12];
    const float* Dp        = (const float*)d_in[13];
    const float* out_w     = (const float*)d_in[14];
    float* out = (float*)d_out;

    float* s = nullptr;
    cudaGetSymbolAddress((void**)&s, g_scratch);
    __half* hs = nullptr;
    cudaGetSymbolAddress((void**)&hs, g_hscratch);

    float* xz     = s + OFF_XZ;
    float* xconv  = s + OFF_XCONV;
    float* dt     = s + OFF_DT;
    float* bcm    = s + OFF_BCM;
    float* merg_p = s + OFF_MERG_P;

    __half* xn16    = hs + HXN;
    __half* xc16    = hs + HXC;
    __half* y16     = hs + HY;
    __half* dtin16  = hs + HDTIN;
    __half* win16   = hs + HWIN;
    __half* wmerg16 = hs + HWMERG;
    __half* wdt16   = hs + HWDT;
    __half* wout16  = hs + HWOUT;

    const int SM64 = 3 * (128 + 64) * 128;    // 73728
    const int SM96 = 3 * (128 + 96) * 128;    // 86016
    cudaFuncSetAttribute(hgemm<64, EPI_NONE,     false>, cudaFuncAttributeMaxDynamicSharedMemorySize, SM64);
    cudaFuncSetAttribute(hgemm<96, EPI_NONE,     true >, cudaFuncAttributeMaxDynamicSharedMemorySize, SM96);
    cudaFuncSetAttribute(hgemm<64, EPI_SOFTPLUS, false>, cudaFuncAttributeMaxDynamicSharedMemorySize, SM64);
    cudaFuncSetAttribute(hgemm<64, EPI_RES,      false>, cudaFuncAttributeMaxDynamicSharedMemorySize, SM64);

    // 0) weight converts (single launch; builds merged [dtin;B;C] too)
    f2h_all<<<(F2H_TOTAL / 8 + 255) / 256, 256>>>(
        in_proj_w, dtin_w, dt_w, B_w, C_w, out_w, hs);

    // 1) LayerNorm -> fp16
    ln_kernel<<<MR, 256>>>(x, ln_g, ln_b, xn16);

    // 2) xz = xn @ in_proj_w^T : (2048, 4096), K=1024
    hgemm<64, EPI_NONE, false><<<dim3(4096 / 64, MR / 128), 256, SM64>>>(
        xn16, win16, xz, MR, 4096, DM_, nullptr, nullptr, 0);

    // 3) causal conv + SiLU -> fp32 + fp16
    conv_silu_kernel<<<(BB * LL * DI_ + 255) / 256, 256>>>(xz, conv_w, conv_b, xconv, xc16);

    // 4) merged [dtin | B | C] partials: (2048, 96), K=2048, split-K=16
    hgemm<96, EPI_NONE, true><<<dim3(1, MR / 128, KSPLIT), 256, SM96>>>(
        xc16, wmerg16, merg_p, MR, 96, DI_, nullptr, nullptr, DI_ / KSPLIT);
    reduce_merged<<<(MR * 96 + 255) / 256, 256>>>(merg_p, dtin16, bcm, dtin_b);

    // 5) dt = softplus(dtin @ dt_w^T + dt_b) : (2048, 2048), K=64
    hgemm<64, EPI_SOFTPLUS, false><<<dim3(DI_ / 64, MR / 128), 256, SM64>>>(
        dtin16, wdt16, dt, MR, DI_, DTR_, dt_b, nullptr, 0);

    // 6) selective scan + SiLU(z) gating -> fp16 y
    scan_kernel<<<(BB * DI_) / 16, 256>>>(xconv, dt, bcm, A_log, Dp, xz, y16);

    // 7) out = y @ out_w^T + residual(x) : (2048, 1024), K=2048
    hgemm<64, EPI_RES, false><<<dim3(DM_ / 64, MR / 128), 256, SM64>>>(
        y16, wout16, out, MR, DM_, DI_, nullptr, x, 0);
}